// round 5
// baseline (speedup 1.0000x reference)
#include <cuda_runtime.h>
#include <math.h>

// ---------------------------------------------------------------------------
// m_btabl, R5: fused kernel with chunked coalesced x staging.
//  * in-kernel max_norm (5 warps, shuffle reductions)
//  * x staged 16 samples/chunk via cp.async.cg (coalesced, 4 chunks/tile)
//    -> GEMM1 reads smem broadcast LDS instead of 7-line LDGs
//  * GEMM2: 2 sample-cols/thread, W1 rows broadcast LDS, packed f32x2
//  * 54KB dynamic smem -> 3 blocks/SM, 15 warps
// ---------------------------------------------------------------------------

#define D1v 40
#define T1v 10
#define D2v 120
#define T2v 5
#define D3v 3

#define BLK 160          // 5 warps: 32 sample-slots x 5 t-cols, 2 samples/thread
#define CHS 16           // samples per staging chunk
#define XSTR 404         // padded stage row stride (floats); 404%32=20 conflict-free

// smem layout (float offsets)
#define SW1   0                      // 4800  scaled BL_W1 [120][40]
#define SBo   4800                   // 600   BL_B [120][5]
#define STW   5400                   // 480   scaled T_W1 transposed+padded [120][4]
#define SW2o  5880                   // 50    scaled BL_W2 [10][5]
#define SWM   5936                   // 25    Wm
#define SW2B  5961                   // 5
#define STBo  5966                   // 3
#define SLAM  5969                   // 1
#define SSC   5970                   // 6 scales
#define SXCH  5984                   // 64*17 = 1088 exchange
#define SXo   7072                   // 16*404 = 6464 staging buffer (16B aligned)
#define SMF   (SXo + CHS*XSTR)       // 13536 floats = 54144 B

typedef unsigned long long ull;

__device__ __forceinline__ ull pk2(float lo, float hi){
    ull r; asm("mov.b64 %0, {%1,%2};" : "=l"(r) : "f"(lo), "f"(hi)); return r;
}
__device__ __forceinline__ float2 upk2(ull v){
    float2 r; asm("mov.b64 {%0,%1}, %2;" : "=f"(r.x), "=f"(r.y) : "l"(v)); return r;
}
__device__ __forceinline__ ull ffma2(ull a, ull b, ull c){
    ull d; asm("fma.rn.f32x2 %0, %1, %2, %3;" : "=l"(d) : "l"(a), "l"(b), "l"(c)); return d;
}
__device__ __forceinline__ ull fmul2(ull a, ull b){
    ull d; asm("mul.rn.f32x2 %0, %1, %2;" : "=l"(d) : "l"(a), "l"(b)); return d;
}
__device__ __forceinline__ ull fadd2(ull a, ull b){
    ull d; asm("add.rn.f32x2 %0, %1, %2;" : "=l"(d) : "l"(a), "l"(b)); return d;
}

// GEMM1 for one column: y1[:, tt] as 20 packed pairs, reading 400 contiguous
// floats at myx (smem). 5 lanes of a sample broadcast; samples at XSTR stride
// hit distinct banks -> ~1 wf per LDS.128.
__device__ __forceinline__ void gemm1_col(const float* __restrict__ myx,
                                          const ull* __restrict__ w2c, ull* y2)
{
    #pragma unroll
    for (int q = 0; q < 20; q++) {
        const ulonglong2* u = (const ulonglong2*)(myx + q * 20);   // 80B steps
        ulonglong2 p0 = u[0];
        ulonglong2 p1 = u[1];
        ulonglong2 p2 = u[2];
        ulonglong2 p3 = u[3];
        ulonglong2 p4 = u[4];
        ull a = fmul2(p0.x, w2c[0]);
        ull b = fmul2(p2.y, w2c[0]);
        a = ffma2(p0.y, w2c[1], a);
        b = ffma2(p3.x, w2c[1], b);
        a = ffma2(p1.x, w2c[2], a);
        b = ffma2(p3.y, w2c[2], b);
        a = ffma2(p1.y, w2c[3], a);
        b = ffma2(p4.x, w2c[3], b);
        a = ffma2(p2.x, w2c[4], a);
        b = ffma2(p4.y, w2c[4], b);
        float2 ca = upk2(a), cb = upk2(b);
        y2[q] = pk2(ca.x + ca.y, cb.x + cb.y);
    }
}

__global__ void __launch_bounds__(BLK, 3)
fused_kernel(const float* __restrict__ x,   const float* __restrict__ W1,
             const float* __restrict__ W2,  const float* __restrict__ Bb,
             const float* __restrict__ TW1, const float* __restrict__ TW,
             const float* __restrict__ TW2, const float* __restrict__ TB,
             const float* __restrict__ l,   float* __restrict__ out, int ntiles)
{
    extern __shared__ float sm[];
    const int tid  = threadIdx.x;
    const int wid  = tid >> 5;
    const int lane = tid & 31;

    // ---- in-kernel max_norm scales: warp w handles matrix w ----
    {
        const float* mp; int n;
        switch (wid) {
            case 0: mp = W1;  n = D2v*D1v; break;
            case 1: mp = TW1; n = D3v*D2v; break;
            case 2: mp = W2;  n = T1v*T2v; break;
            case 3: mp = TW;  n = T2v*T2v; break;
            default: mp = TW2; n = T2v;    break;
        }
        float s = 0.f;
        for (int i = lane; i < n; i += 32) { float v = mp[i]; s += v * v; }
        #pragma unroll
        for (int o = 16; o > 0; o >>= 1) s += __shfl_xor_sync(0xffffffffu, s, o);
        if (lane == 0) {
            float nn = sqrtf(s);
            sm[SSC + wid] = (nn > 10.f) ? (10.f / (1e-8f + nn)) : 1.f;
        }
    }
    __syncthreads();
    const float s1 = sm[SSC+0], s3 = sm[SSC+1], s2 = sm[SSC+2],
                s4 = sm[SSC+3], s5 = sm[SSC+4];

    // ---- scaled weights -> smem ----
    for (int i = tid; i < D2v*D1v; i += BLK) sm[SW1 + i] = W1[i] * s1;
    for (int i = tid; i < D2v*T2v; i += BLK) sm[SBo + i] = Bb[i];
    for (int i = tid; i < D2v*4;   i += BLK) {
        int e = i >> 2, j = i & 3;
        sm[STW + i] = (j < 3) ? TW1[j*D2v + e] * s3 : 0.f;
    }
    if (tid < 50)                     sm[SW2o + tid] = W2[tid] * s2;
    else if (tid >= 64 && tid < 89) {
        int i = tid - 64, r = i / 5, c = i - r * 5;
        sm[SWM + i] = (r == c) ? (1.f / T2v) : TW[i] * s4;
    }
    else if (tid >= 96  && tid < 101) sm[SW2B + (tid - 96)]  = TW2[tid - 96] * s5;
    else if (tid >= 104 && tid < 107) sm[STBo + (tid - 104)] = TB[tid - 104];
    else if (tid == 112) {
        float lv = l[0];
        sm[SLAM] = fminf(fmaxf(lv, 0.f), 1.f);
    }
    __syncthreads();

    const int sl = tid / T2v;        // 0..31 (owns samples sl, sl+32 of tile)
    const int tt = tid - sl * T2v;   // 0..4
    const int ca = sl >> 4;          // chunk holding sample sl       (0/1)
    const int cb = 2 + ca;           // chunk holding sample sl+32    (2/3)
    const int slo = (sl & 15);       // local sample within chunk

    ull w2c[5];
    #pragma unroll
    for (int p = 0; p < 5; p++)
        w2c[p] = pk2(sm[SW2o + (2*p)*T2v + tt], sm[SW2o + (2*p+1)*T2v + tt]);

    for (int t = blockIdx.x; t < ntiles; t += gridDim.x) {
        const long long base = (long long)t * 64;

        // ---- GEMM1 via 4 staged chunks of 16 samples ----
        ull y2a[20], y2b[20];
        #pragma unroll
        for (int c = 0; c < 4; c++) {
            // coalesced stage: 16 samples * 400 floats = 1600 float4
            const float4* src = (const float4*)(x + (base + c * CHS) * (D1v*T1v));
            #pragma unroll
            for (int it = 0; it < 10; it++) {
                int i = tid + it * BLK;          // 0..1599
                int s = i / 100;
                int o = i - s * 100;
                unsigned dst = (unsigned)__cvta_generic_to_shared(
                                   sm + SXo + s * XSTR + o * 4);
                asm volatile("cp.async.cg.shared.global [%0], [%1], 16;"
                             :: "r"(dst), "l"(src + i));
            }
            asm volatile("cp.async.commit_group;");
            asm volatile("cp.async.wait_group 0;" ::: "memory");
            __syncthreads();                     // chunk visible

            if (c == ca) gemm1_col(sm + SXo + slo * XSTR, w2c, y2a);
            if (c == cb) gemm1_col(sm + SXo + slo * XSTR, w2c, y2b);
            __syncthreads();                     // chunk consumed
        }

        // ---- GEMM2 + T_W1 projection (shared broadcast W1 loads) ----
        ull Xa0 = 0ULL, Xa1 = 0ULL, Xb0 = 0ULL, Xb1 = 0ULL;
        const float* bp = sm + SBo + tt;
        #pragma unroll 2
        for (int e = 0; e < D2v; e++) {
            const ulonglong2* wv = (const ulonglong2*)(sm + SW1 + e * D1v);
            ulonglong2 w0 = wv[0];
            ull aa = fmul2(y2a[0], w0.x), ab = fmul2(y2a[1], w0.y);
            ull ba = fmul2(y2b[0], w0.x), bb = fmul2(y2b[1], w0.y);
            #pragma unroll
            for (int i = 1; i < 10; i++) {
                ulonglong2 wi = wv[i];
                aa = ffma2(y2a[2*i],   wi.x, aa);
                ab = ffma2(y2a[2*i+1], wi.y, ab);
                ba = ffma2(y2b[2*i],   wi.x, ba);
                bb = ffma2(y2b[2*i+1], wi.y, bb);
            }
            float bia = bp[e * T2v];
            float2 cc = upk2(fadd2(aa, ab));
            float2 cd = upk2(fadd2(ba, bb));
            float ha = fmaxf(cc.x + cc.y + bia, 0.f);
            float hb = fmaxf(cd.x + cd.y + bia, 0.f);
            ulonglong2 tw = ((const ulonglong2*)(sm + STW))[e];
            ull hda = pk2(ha, ha), hdb = pk2(hb, hb);
            Xa0 = ffma2(tw.x, hda, Xa0);
            Xa1 = ffma2(tw.y, hda, Xa1);
            Xb0 = ffma2(tw.x, hdb, Xb0);
            Xb1 = ffma2(tw.y, hdb, Xb1);
        }

        // ---- exchange X3 (stride 17, conflict-free) ----
        {
            float2 A01 = upk2(Xa0), A2z = upk2(Xa1);
            float2 B01 = upk2(Xb0), B2z = upk2(Xb1);
            float* xca = sm + SXCH + sl * 17;
            float* xcb = sm + SXCH + (sl + 32) * 17;
            xca[0*T2v + tt] = A01.x;
            xca[1*T2v + tt] = A01.y;
            xca[2*T2v + tt] = A2z.x;
            xcb[0*T2v + tt] = B01.x;
            xcb[1*T2v + tt] = B01.y;
            xcb[2*T2v + tt] = B2z.x;
        }
        __syncthreads();

        // ---- per-sample tail (64 threads) ----
        if (tid < 64) {
            const float* xr = sm + SXCH + tid * 17;
            float X[3][5];
            #pragma unroll
            for (int j = 0; j < 3; j++)
                #pragma unroll
                for (int tq = 0; tq < 5; tq++)
                    X[j][tq] = xr[j*5 + tq];

            const float lam = sm[SLAM];
            float o3[3];
            #pragma unroll
            for (int j = 0; j < 3; j++) {
                float P[5];
                #pragma unroll
                for (int tp = 0; tp < 5; tp++) {
                    float s = 0.f;
                    #pragma unroll
                    for (int tq = 0; tq < 5; tq++) s += X[j][tq] * sm[SWM + tq*5 + tp];
                    P[tp] = s;
                }
                float m = P[0];
                #pragma unroll
                for (int tp = 1; tp < 5; tp++) m = fmaxf(m, P[tp]);
                float A[5]; float ssum = 0.f;
                #pragma unroll
                for (int tp = 0; tp < 5; tp++) { A[tp] = __expf(P[tp] - m); ssum += A[tp]; }
                float inv = __fdividef(1.f, ssum);
                float acc = sm[STBo + j];
                #pragma unroll
                for (int tq = 0; tq < 5; tq++) {
                    float Xc = X[j][tq] * (lam + (1.f - lam) * A[tq] * inv);
                    acc += Xc * sm[SW2B + tq];
                }
                o3[j] = acc;
            }
            float m  = fmaxf(o3[0], fmaxf(o3[1], o3[2]));
            float e0 = __expf(o3[0] - m);
            float e1 = __expf(o3[1] - m);
            float e2 = __expf(o3[2] - m);
            float inv = __fdividef(1.f, e0 + e1 + e2);
            long long gs = base + tid;
            out[gs*3 + 0] = e0 * inv;
            out[gs*3 + 1] = e1 * inv;
            out[gs*3 + 2] = e2 * inv;
        }
        __syncthreads();   // exchange reusable
    }
}

// ------------------------------ launch --------------------------------------
extern "C" void kernel_launch(void* const* d_in, const int* in_sizes, int n_in,
                              void* d_out, int out_size)
{
    const float* x   = (const float*)d_in[0];
    const float* W1  = (const float*)d_in[1];
    const float* W2  = (const float*)d_in[2];
    const float* Bb  = (const float*)d_in[3];
    const float* TW1 = (const float*)d_in[4];
    const float* TW  = (const float*)d_in[5];
    const float* TW2 = (const float*)d_in[6];
    const float* TB  = (const float*)d_in[7];
    const float* l   = (const float*)d_in[8];

    const int nsamp  = in_sizes[0] / (D1v * T1v);   // 131072
    const int ntiles = nsamp / 64;                  // 2048

    cudaFuncSetAttribute(fused_kernel, cudaFuncAttributeMaxDynamicSharedMemorySize,
                         SMF * 4);

    int grid = 456;                                 // 3 per SM on 152 SMs
    if (grid > ntiles) grid = ntiles;

    fused_kernel<<<grid, BLK, SMF * 4>>>(x, W1, W2, Bb, TW1, TW, TW2, TB, l,
                                         (float*)d_out, ntiles);
}

// round 6
// speedup vs baseline: 2.3770x; 2.3770x over previous
#include <cuda_runtime.h>
#include <math.h>
#include <stdint.h>

// ---------------------------------------------------------------------------
// m_btabl, R6: tensor-core GEMM2.
//  Per 32-sample tile: H[160x120] = Y1[160x40(pad48)] @ W1^T via
//  mma.sync.m16n8k16 bf16, 2-way truncation split (4 products ~ fp32 accuracy).
//  GEMM1 (fp32 FFMA, direct-global x) writes Y1 straight into A-fragment
//  layout (hi/lo bf16x2) in smem. Epilogue: bias+relu on accumulators,
//  X3 = T_W1 @ H as packed-pair FFMA on (c0,c1) e-pairs + quad shuffle reduce.
//  smem 60KB -> 3 blocks/SM (15 warps).
// ---------------------------------------------------------------------------

#define D1v 40
#define T1v 10
#define D2v 120
#define T2v 5
#define D3v 3

#define BLK 160           // 5 warps; thread tid owns row m=tid (sample tid/5, t=tid%5)
#define SPT 32            // samples per tile (160 rows)
#define NNT 15            // 120/8 n-tiles
#define NKT 3             // 48/16 k-tiles (d padded 40->48 with zeros)

// smem word (u32/float) offsets
#define OW1F  0                      // B frags: [set2][nt15][kt3][lane32][2] = 5760
#define OY1F  5760                   // A frags: [set2][strip10][kt3][rp2][lane32][2] = 7680
#define OBIAS 13440                  // [tt5][pair60][2] = 600
#define OTW1  14040                  // [j3][pair60][2] = 360
#define OW2   14400                  // 50  scaled BL_W2 [10][5]
#define OWM   14450                  // 25
#define OW2B  14475                  // 5
#define OTB   14480                  // 3
#define OLAM  14483                  // 1
#define OSC   14484                  // 6
#define OXCH  14496                  // [sl32][17] = 544
#define SMW   (OXCH + 32*17)         // 15040 words = 60160 B

typedef unsigned long long ull;

__device__ __forceinline__ ull pk2(float lo, float hi){
    ull r; asm("mov.b64 %0, {%1,%2};" : "=l"(r) : "f"(lo), "f"(hi)); return r;
}
__device__ __forceinline__ float2 upk2(ull v){
    float2 r; asm("mov.b64 {%0,%1}, %2;" : "=f"(r.x), "=f"(r.y) : "l"(v)); return r;
}
__device__ __forceinline__ ull ffma2(ull a, ull b, ull c){
    ull d; asm("fma.rn.f32x2 %0, %1, %2, %3;" : "=l"(d) : "l"(a), "l"(b), "l"(c)); return d;
}
__device__ __forceinline__ ull fmul2(ull a, ull b){
    ull d; asm("mul.rn.f32x2 %0, %1, %2;" : "=l"(d) : "l"(a), "l"(b)); return d;
}

__device__ __forceinline__ void mma16816(float* c, uint32_t a0, uint32_t a1,
                                         uint32_t a2, uint32_t a3,
                                         uint32_t b0, uint32_t b1){
    asm("mma.sync.aligned.m16n8k16.row.col.f32.bf16.bf16.f32 "
        "{%0,%1,%2,%3},{%4,%5,%6,%7},{%8,%9},{%0,%1,%2,%3};"
        : "+f"(c[0]), "+f"(c[1]), "+f"(c[2]), "+f"(c[3])
        : "r"(a0), "r"(a1), "r"(a2), "r"(a3), "r"(b0), "r"(b1));
}

// truncation split of (f0,f1) -> bf16x2 hi (exact high 16 bits), bf16x2 lo (rounded residual)
__device__ __forceinline__ void bsplit2(float f0, float f1, uint32_t& hi, uint32_t& lo){
    uint32_t u0 = __float_as_uint(f0), u1 = __float_as_uint(f1);
    asm("prmt.b32 %0, %1, %2, 0x7632;" : "=r"(hi) : "r"(u0), "r"(u1));
    float h0 = __uint_as_float(u0 & 0xffff0000u);
    float h1 = __uint_as_float(u1 & 0xffff0000u);
    float l0 = f0 - h0, l1 = f1 - h1;
    asm("cvt.rn.bf16x2.f32 %0, %1, %2;" : "=r"(lo) : "f"(l1), "f"(l0));
}

// GEMM1 column from global x: 20 packed (y[2q], y[2q+1]) pairs
__device__ __forceinline__ void gemm1_col(const float* __restrict__ myx,
                                          const ull* __restrict__ w2c, ull* y2)
{
    #pragma unroll
    for (int q = 0; q < 20; q++) {
        const ulonglong2* u = (const ulonglong2*)(myx + q * 20);
        ulonglong2 p0 = u[0];
        ulonglong2 p1 = u[1];
        ulonglong2 p2 = u[2];
        ulonglong2 p3 = u[3];
        ulonglong2 p4 = u[4];
        ull a = fmul2(p0.x, w2c[0]);
        ull b = fmul2(p2.y, w2c[0]);
        a = ffma2(p0.y, w2c[1], a);
        b = ffma2(p3.x, w2c[1], b);
        a = ffma2(p1.x, w2c[2], a);
        b = ffma2(p3.y, w2c[2], b);
        a = ffma2(p1.y, w2c[3], a);
        b = ffma2(p4.x, w2c[3], b);
        a = ffma2(p2.x, w2c[4], a);
        b = ffma2(p4.y, w2c[4], b);
        float2 ca = upk2(a), cb = upk2(b);
        y2[q] = pk2(ca.x + ca.y, cb.x + cb.y);
    }
}

__global__ void __launch_bounds__(BLK, 3)
fused_kernel(const float* __restrict__ x,   const float* __restrict__ W1,
             const float* __restrict__ W2,  const float* __restrict__ Bb,
             const float* __restrict__ TW1, const float* __restrict__ TW,
             const float* __restrict__ TW2, const float* __restrict__ TB,
             const float* __restrict__ l,   float* __restrict__ out, int ntiles)
{
    extern __shared__ float sm[];
    uint32_t* smu = (uint32_t*)sm;
    const int tid  = threadIdx.x;
    const int wid  = tid >> 5;
    const int lane = tid & 31;

    // ---- max_norm scales (warp w -> matrix w) ----
    {
        const float* mp; int n;
        switch (wid) {
            case 0: mp = W1;  n = D2v*D1v; break;
            case 1: mp = TW1; n = D3v*D2v; break;
            case 2: mp = W2;  n = T1v*T2v; break;
            case 3: mp = TW;  n = T2v*T2v; break;
            default: mp = TW2; n = T2v;    break;
        }
        float s = 0.f;
        for (int i = lane; i < n; i += 32) { float v = mp[i]; s += v * v; }
        #pragma unroll
        for (int o = 16; o > 0; o >>= 1) s += __shfl_xor_sync(0xffffffffu, s, o);
        if (lane == 0) {
            float nn = sqrtf(s);
            sm[OSC + wid] = (nn > 10.f) ? (10.f / (1e-8f + nn)) : 1.f;
        }
    }
    __syncthreads();
    const float s1 = sm[OSC+0], s3 = sm[OSC+1], s2 = sm[OSC+2],
                s4 = sm[OSC+3], s5 = sm[OSC+4];

    // ---- producers ----
    // B fragments (W1^T, hi/lo): item = (nt,kt,lane,rp)
    for (int i = tid; i < NNT*NKT*32*2; i += BLK) {
        int rp = i & 1, li = (i >> 1) & 31;
        int ktc = (i >> 6) % NKT, nt = (i >> 6) / NKT;
        int g = li >> 2, tl = li & 3;
        int e  = nt*8 + g;
        int k0 = ktc*16 + rp*8 + 2*tl;
        float w0 = (k0   < D1v) ? W1[e*D1v + k0    ] * s1 : 0.f;
        float w1 = (k0+1 < D1v) ? W1[e*D1v + k0 + 1] * s1 : 0.f;
        uint32_t hi, lo; bsplit2(w0, w1, hi, lo);
        int word = ((nt*NKT + ktc)*32 + li)*2 + rp;
        smu[OW1F + word]        = hi;
        smu[OW1F + 2880 + word] = lo;
    }
    // zero A-frag region (covers kt2/rp1 zero padding)
    for (int i = tid; i < 7680; i += BLK) smu[OY1F + i] = 0;
    // bias pairs [tt][pair][2]
    for (int i = tid; i < 600; i += BLK) {
        int tt = i / 120, rem = i - tt*120;
        int p = rem >> 1, half = rem & 1;
        sm[OBIAS + (tt*60 + p)*2 + half] = Bb[(2*p + half)*T2v + tt];
    }
    // TW1 pairs [j][pair][2]
    for (int i = tid; i < 360; i += BLK) {
        int j = i / 120, rem = i - j*120;
        int p = rem >> 1, half = rem & 1;
        sm[OTW1 + (j*60 + p)*2 + half] = TW1[j*D2v + 2*p + half] * s3;
    }
    if (tid < 50)                     sm[OW2 + tid] = W2[tid] * s2;
    else if (tid >= 64 && tid < 89) {
        int i = tid - 64, r = i / 5, c = i - r*5;
        sm[OWM + i] = (r == c) ? (1.f / T2v) : TW[i] * s4;
    }
    else if (tid >= 96  && tid < 101) sm[OW2B + (tid - 96)]  = TW2[tid - 96] * s5;
    else if (tid >= 104 && tid < 107) sm[OTB  + (tid - 104)] = TB[tid - 104];
    else if (tid == 112) {
        float lv = l[0];
        sm[OLAM] = fminf(fmaxf(lv, 0.f), 1.f);
    }
    __syncthreads();

    // ---- per-thread constants ----
    const int m   = tid;            // row index in the 160-row tile
    const int sl  = m / T2v;        // sample slot 0..31
    const int tt  = m - sl * T2v;   // t-column 0..4
    const int r16 = m & 15;
    // scatter base: word = base_r + per-q constant
    const int base_r = (m >> 4) * 384 + (r16 & 7) * 8 + ((r16 < 8) ? 0 : 1);

    ull w2c[5];
    #pragma unroll
    for (int p = 0; p < 5; p++)
        w2c[p] = pk2(sm[OW2 + (2*p)*T2v + tt], sm[OW2 + (2*p+1)*T2v + tt]);

    const int g  = lane >> 2;       // mma row group
    const int tl = lane & 3;        // mma col group

    for (int t = blockIdx.x; t < ntiles; t += gridDim.x) {
        const long long base = (long long)t * SPT;

        // ================= GEMM1 + scatter to A-fragment layout =============
        {
            ull y2[20];
            gemm1_col(x + (base + sl) * (D1v*T1v), w2c, y2);
            __syncthreads();   // prior tile fully done (A-frag reads, xch tail)
            #pragma unroll
            for (int q = 0; q < 20; q++) {
                float2 v = upk2(y2[q]);
                uint32_t hi, lo; bsplit2(v.x, v.y, hi, lo);
                const int kt   = q >> 3;
                const int kk   = 2*q - kt*16;
                const int rp   = kk >> 3;
                const int tsel = (kk & 7) >> 1;
                const int word = base_r + (kt*2 + rp)*64 + tsel*2;
                smu[OY1F + word]        = hi;
                smu[OY1F + 3840 + word] = lo;
            }
        }
        __syncthreads();       // Y1 fragments ready

        // ================= tensor GEMM2 + epilogue, 2 strips per warp =======
        for (int sidx = 0; sidx < 2; sidx++) {
            const int s = wid*2 + sidx;
            float acc[NNT][4];
            #pragma unroll
            for (int nt = 0; nt < NNT; nt++) {
                acc[nt][0] = 0.f; acc[nt][1] = 0.f;
                acc[nt][2] = 0.f; acc[nt][3] = 0.f;
            }
            #pragma unroll
            for (int kt = 0; kt < NKT; kt++) {
                const int abase = OY1F + (((s*NKT + kt)*2)*32 + lane)*2;
                uint2 Ah01 = *(const uint2*)(smu + abase);
                uint2 Ah23 = *(const uint2*)(smu + abase + 64);
                uint2 Al01 = *(const uint2*)(smu + abase + 3840);
                uint2 Al23 = *(const uint2*)(smu + abase + 3840 + 64);
                #pragma unroll
                for (int nt = 0; nt < NNT; nt++) {
                    const int bbase = OW1F + ((nt*NKT + kt)*32 + lane)*2;
                    uint2 Bh = *(const uint2*)(smu + bbase);
                    uint2 Bl = *(const uint2*)(smu + bbase + 2880);
                    mma16816(acc[nt], Ah01.x, Ah01.y, Ah23.x, Ah23.y, Bh.x, Bh.y);
                    mma16816(acc[nt], Ah01.x, Ah01.y, Ah23.x, Ah23.y, Bl.x, Bl.y);
                    mma16816(acc[nt], Al01.x, Al01.y, Al23.x, Al23.y, Bh.x, Bh.y);
                    mma16816(acc[nt], Al01.x, Al01.y, Al23.x, Al23.y, Bl.x, Bl.y);
                }
            }
            // ---- epilogue: bias + relu + X3 projection ----
            const int m0 = s*16 + g, m1 = m0 + 8;
            const int tt0 = m0 % 5, sl0 = m0 / 5;
            const int tt1 = m1 % 5, sl1 = m1 / 5;
            ull Xp[6] = {0,0,0,0,0,0};      // [row0 j0..2 | row1 j0..2]
            #pragma unroll
            for (int nt = 0; nt < NNT; nt++) {
                const int pi = nt*4 + tl;   // e-pair index
                float2 b0 = *(const float2*)(sm + OBIAS + (tt0*60 + pi)*2);
                float2 b1 = *(const float2*)(sm + OBIAS + (tt1*60 + pi)*2);
                float h00 = fmaxf(acc[nt][0] + b0.x, 0.f);
                float h01 = fmaxf(acc[nt][1] + b0.y, 0.f);
                float h10 = fmaxf(acc[nt][2] + b1.x, 0.f);
                float h11 = fmaxf(acc[nt][3] + b1.y, 0.f);
                ull hp0 = pk2(h00, h01), hp1 = pk2(h10, h11);
                #pragma unroll
                for (int j = 0; j < 3; j++) {
                    ull tw = *(const ull*)(sm + OTW1 + (j*60 + pi)*2);
                    Xp[j]   = ffma2(hp0, tw, Xp[j]);
                    Xp[3+j] = ffma2(hp1, tw, Xp[3+j]);
                }
            }
            #pragma unroll
            for (int j = 0; j < 3; j++) {
                float2 c0 = upk2(Xp[j]);
                float2 c1 = upk2(Xp[3+j]);
                float r0 = c0.x + c0.y;
                float r1 = c1.x + c1.y;
                r0 += __shfl_xor_sync(0xffffffffu, r0, 1);
                r0 += __shfl_xor_sync(0xffffffffu, r0, 2);
                r1 += __shfl_xor_sync(0xffffffffu, r1, 1);
                r1 += __shfl_xor_sync(0xffffffffu, r1, 2);
                if (tl == 0) {
                    sm[OXCH + sl0*17 + tt0*3 + j] = r0;
                    sm[OXCH + sl1*17 + tt1*3 + j] = r1;
                }
            }
        }
        __syncthreads();       // X3 exchange ready

        // ================= per-sample tail (32 threads) ======================
        if (tid < SPT) {
            const float* xr = sm + OXCH + tid * 17;
            float X[3][5];
            #pragma unroll
            for (int j = 0; j < 3; j++)
                #pragma unroll
                for (int tq = 0; tq < 5; tq++)
                    X[j][tq] = xr[tq*3 + j];

            const float lam = sm[OLAM];
            float o3[3];
            #pragma unroll
            for (int j = 0; j < 3; j++) {
                float P[5];
                #pragma unroll
                for (int tp = 0; tp < 5; tp++) {
                    float s = 0.f;
                    #pragma unroll
                    for (int tq = 0; tq < 5; tq++) s += X[j][tq] * sm[OWM + tq*5 + tp];
                    P[tp] = s;
                }
                float mx = P[0];
                #pragma unroll
                for (int tp = 1; tp < 5; tp++) mx = fmaxf(mx, P[tp]);
                float A[5]; float ssum = 0.f;
                #pragma unroll
                for (int tp = 0; tp < 5; tp++) { A[tp] = __expf(P[tp] - mx); ssum += A[tp]; }
                float inv = __fdividef(1.f, ssum);
                float acc2 = sm[OTB + j];
                #pragma unroll
                for (int tq = 0; tq < 5; tq++) {
                    float Xc = X[j][tq] * (lam + (1.f - lam) * A[tq] * inv);
                    acc2 += Xc * sm[OW2B + tq];
                }
                o3[j] = acc2;
            }
            float mx = fmaxf(o3[0], fmaxf(o3[1], o3[2]));
            float e0 = __expf(o3[0] - mx);
            float e1 = __expf(o3[1] - mx);
            float e2 = __expf(o3[2] - mx);
            float inv = __fdividef(1.f, e0 + e1 + e2);
            long long gs = base + tid;
            out[gs*3 + 0] = e0 * inv;
            out[gs*3 + 1] = e1 * inv;
            out[gs*3 + 2] = e2 * inv;
        }
        // loop-top __syncthreads (inside GEMM1 block) orders tail vs next scatter
    }
}

// ------------------------------ launch --------------------------------------
extern "C" void kernel_launch(void* const* d_in, const int* in_sizes, int n_in,
                              void* d_out, int out_size)
{
    const float* x   = (const float*)d_in[0];
    const float* W1  = (const float*)d_in[1];
    const float* W2  = (const float*)d_in[2];
    const float* Bb  = (const float*)d_in[3];
    const float* TW1 = (const float*)d_in[4];
    const float* TW  = (const float*)d_in[5];
    const float* TW2 = (const float*)d_in[6];
    const float* TB  = (const float*)d_in[7];
    const float* l   = (const float*)d_in[8];

    const int nsamp  = in_sizes[0] / (D1v * T1v);   // 131072
    const int ntiles = nsamp / SPT;                 // 4096

    cudaFuncSetAttribute(fused_kernel, cudaFuncAttributeMaxDynamicSharedMemorySize,
                         SMW * 4);

    int grid = 456;                                 // 3 per SM on 152 SMs
    if (grid > ntiles) grid = ntiles;

    fused_kernel<<<grid, BLK, SMW * 4>>>(x, W1, W2, Bb, TW1, TW, TW2, TB, l,
                                         (float*)d_out, ntiles);
}

// round 7
// speedup vs baseline: 2.7084x; 1.1394x over previous
#include <cuda_runtime.h>
#include <math.h>
#include <stdint.h>

// ---------------------------------------------------------------------------
// m_btabl, R7: tensor-core GEMM2 + staged x + 16-sample tiles.
//  * x staged per 16-sample tile via cp.async (coalesced), single buffer,
//    stage(t+1) overlapped under mma(t).
//  * GEMM1: 2 threads per y1-column (d-halves), reads staged smem.
//  * GEMM2: H[80x120] = Y1[80x48] @ W1^T, mma m16n8k16 bf16, 3-product split
//    (hi*hi + hi*lo + lo*hi). 1 strip per warp.
//  * 68KB smem -> 3 blocks/SM (15 warps).
// ---------------------------------------------------------------------------

#define D1v 40
#define T1v 10
#define D2v 120
#define T2v 5
#define D3v 3

#define BLK 160           // 5 warps
#define SPT 16            // samples per tile (80 rows, 5 m16-strips)
#define NNT 15            // 120/8 n-tiles
#define NKT 3             // 48/16 k-tiles
#define XSTR 404          // staged x row stride (floats)

// smem word offsets
#define OW1F  0                       // B frags hi [nt15][kt3][lane32][2]=2880, lo +2880
#define OY1F  5760                    // A frags hi [s5][kt3][rp2][lane32][2]=1920, lo +1920
#define OBIAS 9600                    // [tt5][pair60][2] = 600
#define OTW1  10200                   // [j3][pair60][2] = 360
#define OW2   10560                   // 50
#define OWM   10610                   // 25
#define OW2B  10635                   // 5
#define OTB   10640                   // 3
#define OLAM  10643                   // 1
#define OSC   10644                   // 6
#define OXCH  10656                   // 16*17 = 272
#define OXB   10944                   // x buffer 16*404 = 6464
#define SMW   (OXB + SPT*XSTR)        // 17408 words = 69632 B

typedef unsigned long long ull;

__device__ __forceinline__ ull pk2(float lo, float hi){
    ull r; asm("mov.b64 %0, {%1,%2};" : "=l"(r) : "f"(lo), "f"(hi)); return r;
}
__device__ __forceinline__ float2 upk2(ull v){
    float2 r; asm("mov.b64 {%0,%1}, %2;" : "=f"(r.x), "=f"(r.y) : "l"(v)); return r;
}
__device__ __forceinline__ ull ffma2(ull a, ull b, ull c){
    ull d; asm("fma.rn.f32x2 %0, %1, %2, %3;" : "=l"(d) : "l"(a), "l"(b), "l"(c)); return d;
}
__device__ __forceinline__ ull fmul2(ull a, ull b){
    ull d; asm("mul.rn.f32x2 %0, %1, %2;" : "=l"(d) : "l"(a), "l"(b)); return d;
}

__device__ __forceinline__ void mma16816(float* c, uint32_t a0, uint32_t a1,
                                         uint32_t a2, uint32_t a3,
                                         uint32_t b0, uint32_t b1){
    asm("mma.sync.aligned.m16n8k16.row.col.f32.bf16.bf16.f32 "
        "{%0,%1,%2,%3},{%4,%5,%6,%7},{%8,%9},{%0,%1,%2,%3};"
        : "+f"(c[0]), "+f"(c[1]), "+f"(c[2]), "+f"(c[3])
        : "r"(a0), "r"(a1), "r"(a2), "r"(a3), "r"(b0), "r"(b1));
}

// truncation split: hi = top-16-bits bf16x2 (exact), lo = rn(residual) bf16x2
__device__ __forceinline__ void bsplit2(float f0, float f1, uint32_t& hi, uint32_t& lo){
    uint32_t u0 = __float_as_uint(f0), u1 = __float_as_uint(f1);
    asm("prmt.b32 %0, %1, %2, 0x7632;" : "=r"(hi) : "r"(u0), "r"(u1));
    float h0 = __uint_as_float(u0 & 0xffff0000u);
    float h1 = __uint_as_float(u1 & 0xffff0000u);
    float l0 = f0 - h0, l1 = f1 - h1;
    asm("cvt.rn.bf16x2.f32 %0, %1, %2;" : "=r"(lo) : "f"(l1), "f"(l0));
}

__global__ void __launch_bounds__(BLK, 3)
fused_kernel(const float* __restrict__ x,   const float* __restrict__ W1,
             const float* __restrict__ W2,  const float* __restrict__ Bb,
             const float* __restrict__ TW1, const float* __restrict__ TW,
             const float* __restrict__ TW2, const float* __restrict__ TB,
             const float* __restrict__ l,   float* __restrict__ out, int ntiles)
{
    extern __shared__ float sm[];
    uint32_t* smu = (uint32_t*)sm;
    const int tid  = threadIdx.x;
    const int wid  = tid >> 5;
    const int lane = tid & 31;

    // ---- stage helper: 16 samples * 400 floats, coalesced ----
    auto stage = [&](long long tile){
        const float4* src = (const float4*)(x + tile * (SPT * D1v * T1v));
        #pragma unroll
        for (int it = 0; it < 10; it++) {
            int i = tid + it * BLK;          // 0..1599
            int s = i / 100;
            int o = i - s * 100;
            unsigned dst = (unsigned)__cvta_generic_to_shared(
                               sm + OXB + s * XSTR + o * 4);
            asm volatile("cp.async.cg.shared.global [%0], [%1], 16;"
                         :: "r"(dst), "l"(src + i));
        }
        asm volatile("cp.async.commit_group;");
    };

    const long long tile0 = blockIdx.x;   // grid-stride by gridDim.x
    if (tile0 < ntiles) stage(tile0);     // prefetch first tile

    // ---- max_norm scales (warp w -> matrix w) ----
    {
        const float* mp; int n;
        switch (wid) {
            case 0: mp = W1;  n = D2v*D1v; break;
            case 1: mp = TW1; n = D3v*D2v; break;
            case 2: mp = W2;  n = T1v*T2v; break;
            case 3: mp = TW;  n = T2v*T2v; break;
            default: mp = TW2; n = T2v;    break;
        }
        float s = 0.f;
        for (int i = lane; i < n; i += 32) { float v = mp[i]; s += v * v; }
        #pragma unroll
        for (int o = 16; o > 0; o >>= 1) s += __shfl_xor_sync(0xffffffffu, s, o);
        if (lane == 0) {
            float nn = sqrtf(s);
            sm[OSC + wid] = (nn > 10.f) ? (10.f / (1e-8f + nn)) : 1.f;
        }
    }
    __syncthreads();
    const float s1 = sm[OSC+0], s3 = sm[OSC+1], s2 = sm[OSC+2],
                s4 = sm[OSC+3], s5 = sm[OSC+4];

    // ---- weight producers ----
    for (int i = tid; i < NNT*NKT*32*2; i += BLK) {
        int rp = i & 1, li = (i >> 1) & 31;
        int ktc = (i >> 6) % NKT, nt = (i >> 6) / NKT;
        int g = li >> 2, tl2 = li & 3;
        int e  = nt*8 + g;
        int k0 = ktc*16 + rp*8 + 2*tl2;
        float w0 = (k0   < D1v) ? W1[e*D1v + k0    ] * s1 : 0.f;
        float w1 = (k0+1 < D1v) ? W1[e*D1v + k0 + 1] * s1 : 0.f;
        uint32_t hi, lo; bsplit2(w0, w1, hi, lo);
        int word = ((nt*NKT + ktc)*32 + li)*2 + rp;
        smu[OW1F + word]        = hi;
        smu[OW1F + 2880 + word] = lo;
    }
    // zero A-frag padding slot (kt=2, rp=1) hi+lo, all strips
    for (int i = tid; i < 5*64; i += BLK) {
        int s = i >> 6, o = i & 63;
        int word = ((s*NKT + 2)*2 + 1)*64 + o;
        smu[OY1F + word]        = 0;
        smu[OY1F + 1920 + word] = 0;
    }
    for (int i = tid; i < 600; i += BLK) {
        int tt = i / 120, rem = i - tt*120;
        int p = rem >> 1, half = rem & 1;
        sm[OBIAS + (tt*60 + p)*2 + half] = Bb[(2*p + half)*T2v + tt];
    }
    for (int i = tid; i < 360; i += BLK) {
        int j = i / 120, rem = i - j*120;
        int p = rem >> 1, half = rem & 1;
        sm[OTW1 + (j*60 + p)*2 + half] = TW1[j*D2v + 2*p + half] * s3;
    }
    if (tid < 50)                     sm[OW2 + tid] = W2[tid] * s2;
    else if (tid >= 64 && tid < 89) {
        int i = tid - 64, r = i / 5, c = i - r*5;
        sm[OWM + i] = (r == c) ? (1.f / T2v) : TW[i] * s4;
    }
    else if (tid >= 96  && tid < 101) sm[OW2B + (tid - 96)]  = TW2[tid - 96] * s5;
    else if (tid >= 104 && tid < 107) sm[OTB  + (tid - 104)] = TB[tid - 104];
    else if (tid == 112) {
        float lv = l[0];
        sm[OLAM] = fminf(fmaxf(lv, 0.f), 1.f);
    }

    // ---- per-thread GEMM1/scatter constants ----
    const int c    = tid >> 1;         // column 0..79 == row m'
    const int dh   = tid & 1;          // d-half (0: d0..19, 1: d20..39)
    const int slg  = c / T2v;          // sample 0..15
    const int ttg  = c - slg * T2v;    // t-col 0..4
    const int st_  = c >> 4;           // strip of row m'
    const int r16  = c & 15;
    const int wbase = ((r16 & 7) * 4) * 2 + (r16 >> 3);

    __syncthreads();                   // weights ready

    ull w2c[5];
    #pragma unroll
    for (int p = 0; p < 5; p++)
        w2c[p] = pk2(sm[OW2 + (2*p)*T2v + ttg], sm[OW2 + (2*p+1)*T2v + ttg]);

    const int g  = lane >> 2;          // mma row group
    const int tl = lane & 3;           // mma col group
    // epilogue row constants (strip = wid)
    const int m0  = wid*16 + g, m1 = m0 + 8;
    const int tt0 = m0 % 5, sl0 = m0 / 5;
    const int tt1 = m1 % 5, sl1 = m1 / 5;

    for (long long t = tile0; t < ntiles; t += gridDim.x) {
        asm volatile("cp.async.wait_group 0;" ::: "memory");
        __syncthreads();               // x(t) visible; prior tile fully done

        // ---- GEMM1: half-column from staged x ----
        ull y2[10];
        {
            const float* myx = sm + OXB + slg * XSTR + dh * 200;
            #pragma unroll
            for (int q = 0; q < 10; q++) {
                const ulonglong2* u = (const ulonglong2*)(myx + q * 20);
                ulonglong2 p0 = u[0];
                ulonglong2 p1 = u[1];
                ulonglong2 p2 = u[2];
                ulonglong2 p3 = u[3];
                ulonglong2 p4 = u[4];
                ull a = fmul2(p0.x, w2c[0]);
                ull b = fmul2(p2.y, w2c[0]);
                a = ffma2(p0.y, w2c[1], a);
                b = ffma2(p3.x, w2c[1], b);
                a = ffma2(p1.x, w2c[2], a);
                b = ffma2(p3.y, w2c[2], b);
                a = ffma2(p1.y, w2c[3], a);
                b = ffma2(p4.x, w2c[3], b);
                a = ffma2(p2.x, w2c[4], a);
                b = ffma2(p4.y, w2c[4], b);
                float2 ca = upk2(a), cb = upk2(b);
                y2[q] = pk2(ca.x + ca.y, cb.x + cb.y);
            }
        }
        __syncthreads();               // x buffer fully consumed

        if (t + gridDim.x < ntiles) stage(t + gridDim.x);   // overlap with mma

        // ---- scatter y2 into A-fragment layout ----
        #pragma unroll
        for (int q = 0; q < 10; q++) {
            const int qp   = dh*10 + q;
            const int kt   = qp >> 3;
            const int rp   = (qp >> 2) & 1;
            const int tsel = qp & 3;
            const int word = ((st_*NKT + kt)*2 + rp)*64 + wbase + tsel*2;
            float2 v = upk2(y2[q]);
            uint32_t hi, lo; bsplit2(v.x, v.y, hi, lo);
            smu[OY1F + word]        = hi;
            smu[OY1F + 1920 + word] = lo;
        }
        __syncthreads();               // A-frags ready

        // ---- tensor GEMM2 (strip = wid) + epilogue ----
        {
            float acc[NNT][4];
            #pragma unroll
            for (int nt = 0; nt < NNT; nt++) {
                acc[nt][0] = 0.f; acc[nt][1] = 0.f;
                acc[nt][2] = 0.f; acc[nt][3] = 0.f;
            }
            #pragma unroll
            for (int kt = 0; kt < NKT; kt++) {
                const int abase = OY1F + ((wid*NKT + kt)*2)*64 + lane*2;
                uint2 Ah01 = *(const uint2*)(smu + abase);
                uint2 Ah23 = *(const uint2*)(smu + abase + 64);
                uint2 Al01 = *(const uint2*)(smu + abase + 1920);
                uint2 Al23 = *(const uint2*)(smu + abase + 1920 + 64);
                #pragma unroll
                for (int nt = 0; nt < NNT; nt++) {
                    const int bbase = OW1F + ((nt*NKT + kt)*32 + lane)*2;
                    uint2 Bh = *(const uint2*)(smu + bbase);
                    uint2 Bl = *(const uint2*)(smu + bbase + 2880);
                    mma16816(acc[nt], Ah01.x, Ah01.y, Ah23.x, Ah23.y, Bh.x, Bh.y);
                    mma16816(acc[nt], Ah01.x, Ah01.y, Ah23.x, Ah23.y, Bl.x, Bl.y);
                    mma16816(acc[nt], Al01.x, Al01.y, Al23.x, Al23.y, Bh.x, Bh.y);
                }
            }
            // bias + relu + X3 projection
            ull Xp[6] = {0,0,0,0,0,0};
            #pragma unroll
            for (int nt = 0; nt < NNT; nt++) {
                const int pi = nt*4 + tl;
                float2 b0 = *(const float2*)(sm + OBIAS + (tt0*60 + pi)*2);
                float2 b1 = *(const float2*)(sm + OBIAS + (tt1*60 + pi)*2);
                float h00 = fmaxf(acc[nt][0] + b0.x, 0.f);
                float h01 = fmaxf(acc[nt][1] + b0.y, 0.f);
                float h10 = fmaxf(acc[nt][2] + b1.x, 0.f);
                float h11 = fmaxf(acc[nt][3] + b1.y, 0.f);
                ull hp0 = pk2(h00, h01), hp1 = pk2(h10, h11);
                #pragma unroll
                for (int j = 0; j < 3; j++) {
                    ull tw = *(const ull*)(sm + OTW1 + (j*60 + pi)*2);
                    Xp[j]   = ffma2(hp0, tw, Xp[j]);
                    Xp[3+j] = ffma2(hp1, tw, Xp[3+j]);
                }
            }
            #pragma unroll
            for (int j = 0; j < 3; j++) {
                float2 c0 = upk2(Xp[j]);
                float2 c1 = upk2(Xp[3+j]);
                float r0 = c0.x + c0.y;
                float r1 = c1.x + c1.y;
                r0 += __shfl_xor_sync(0xffffffffu, r0, 1);
                r0 += __shfl_xor_sync(0xffffffffu, r0, 2);
                r1 += __shfl_xor_sync(0xffffffffu, r1, 1);
                r1 += __shfl_xor_sync(0xffffffffu, r1, 2);
                if (tl == 0) {
                    sm[OXCH + sl0*17 + tt0*3 + j] = r0;
                    sm[OXCH + sl1*17 + tt1*3 + j] = r1;
                }
            }
        }
        __syncthreads();               // xch ready

        // ---- per-sample tail (16 threads) ----
        if (tid < SPT) {
            const float* xr = sm + OXCH + tid * 17;
            float X[3][5];
            #pragma unroll
            for (int j = 0; j < 3; j++)
                #pragma unroll
                for (int tq = 0; tq < 5; tq++)
                    X[j][tq] = xr[tq*3 + j];

            const float lam = sm[OLAM];
            float o3[3];
            #pragma unroll
            for (int j = 0; j < 3; j++) {
                float P[5];
                #pragma unroll
                for (int tp = 0; tp < 5; tp++) {
                    float s = 0.f;
                    #pragma unroll
                    for (int tq = 0; tq < 5; tq++) s += X[j][tq] * sm[OWM + tq*5 + tp];
                    P[tp] = s;
                }
                float mx = P[0];
                #pragma unroll
                for (int tp = 1; tp < 5; tp++) mx = fmaxf(mx, P[tp]);
                float A[5]; float ssum = 0.f;
                #pragma unroll
                for (int tp = 0; tp < 5; tp++) { A[tp] = __expf(P[tp] - mx); ssum += A[tp]; }
                float inv = __fdividef(1.f, ssum);
                float acc2 = sm[OTB + j];
                #pragma unroll
                for (int tq = 0; tq < 5; tq++) {
                    float Xc = X[j][tq] * (lam + (1.f - lam) * A[tq] * inv);
                    acc2 += Xc * sm[OW2B + tq];
                }
                o3[j] = acc2;
            }
            float mx = fmaxf(o3[0], fmaxf(o3[1], o3[2]));
            float e0 = __expf(o3[0] - mx);
            float e1 = __expf(o3[1] - mx);
            float e2 = __expf(o3[2] - mx);
            float inv = __fdividef(1.f, e0 + e1 + e2);
            long long gs = t * SPT + tid;
            out[gs*3 + 0] = e0 * inv;
            out[gs*3 + 1] = e1 * inv;
            out[gs*3 + 2] = e2 * inv;
        }
        // top-of-loop sync orders tail before next scatter/xch overwrite
    }
}

// ------------------------------ launch --------------------------------------
extern "C" void kernel_launch(void* const* d_in, const int* in_sizes, int n_in,
                              void* d_out, int out_size)
{
    const float* x   = (const float*)d_in[0];
    const float* W1  = (const float*)d_in[1];
    const float* W2  = (const float*)d_in[2];
    const float* Bb  = (const float*)d_in[3];
    const float* TW1 = (const float*)d_in[4];
    const float* TW  = (const float*)d_in[5];
    const float* TW2 = (const float*)d_in[6];
    const float* TB  = (const float*)d_in[7];
    const float* l   = (const float*)d_in[8];

    const int nsamp  = in_sizes[0] / (D1v * T1v);   // 131072
    const int ntiles = nsamp / SPT;                 // 8192

    cudaFuncSetAttribute(fused_kernel, cudaFuncAttributeMaxDynamicSharedMemorySize,
                         SMW * 4);

    int grid = 456;                                 // 3 per SM on 152 SMs
    if (grid > ntiles) grid = ntiles;

    fused_kernel<<<grid, BLK, SMW * 4>>>(x, W1, W2, Bb, TW1, TW, TW2, TB, l,
                                         (float*)d_out, ntiles);
}

// round 8
// speedup vs baseline: 2.7823x; 1.0273x over previous
#include <cuda_runtime.h>
#include <math.h>
#include <stdint.h>

// ---------------------------------------------------------------------------
// m_btabl, R8: read-once GEMM1 + B-fragments-in-registers mma.
//  * x staged per 16-sample tile (cp.async, overlapped with mma of prev tile)
//  * GEMM1: thread owns 4 d-rows of one sample -> reads x ONCE, computes
//    y1[4][5] fully, scatters to A-fragment layout (stride-66 blocks).
//  * GEMM2: warp owns 3 n-tiles x ALL 5 strips; B frags live in 36 registers
//    loaded once. mma smem traffic = A fragments only.
//  * Epilogue: per-warp partial X3 -> smem part[80][3][5]; tail sums 5 warps.
//  * 69KB smem -> 3 blocks/SM (15 warps).
// ---------------------------------------------------------------------------

#define D1v 40
#define T1v 10
#define D2v 120
#define T2v 5
#define D3v 3

#define BLK 160           // 5 warps
#define SPT 16            // samples per tile (80 rows, 5 m16-strips)
#define NKT 3             // 48/16 k-tiles (d padded 40->48)
#define XSTR 404          // staged x row stride (floats)
#define ABLK 66           // A-frag block stride (64 used + 2 pad, kills conflicts)

// smem word offsets
#define OW1F  0                       // B frags hi 2880 / lo +2880 (PROLOGUE ONLY)
#define OPART 0                       // aliases OW1F after prologue: [80][3][5]=1200
#define OY1F  5760                    // A frags hi [s5][kt3][rp2][66]=1980, lo +1980
#define OBIAS 9720                    // [tt5][pair60][2] = 600
#define OTW1  10320                   // [j3][pair60][2] = 360
#define OW2   10680                   // 50 scaled BL_W2 [k10][t5]
#define OWM   10730                   // 25
#define OW2B  10755                   // 5
#define OTB   10760                   // 3
#define OLAM  10763                   // 1
#define OSC   10764                   // 6
#define OXB   10784                   // x buffer 16*404 = 6464 (16B aligned)
#define SMW   (OXB + SPT*XSTR)        // 17248 words = 68992 B

typedef unsigned long long ull;

__device__ __forceinline__ ull pk2(float lo, float hi){
    ull r; asm("mov.b64 %0, {%1,%2};" : "=l"(r) : "f"(lo), "f"(hi)); return r;
}
__device__ __forceinline__ float2 upk2(ull v){
    float2 r; asm("mov.b64 {%0,%1}, %2;" : "=f"(r.x), "=f"(r.y) : "l"(v)); return r;
}
__device__ __forceinline__ ull ffma2(ull a, ull b, ull c){
    ull d; asm("fma.rn.f32x2 %0, %1, %2, %3;" : "=l"(d) : "l"(a), "l"(b), "l"(c)); return d;
}

__device__ __forceinline__ void mma16816(float* c, uint32_t a0, uint32_t a1,
                                         uint32_t a2, uint32_t a3,
                                         uint32_t b0, uint32_t b1){
    asm("mma.sync.aligned.m16n8k16.row.col.f32.bf16.bf16.f32 "
        "{%0,%1,%2,%3},{%4,%5,%6,%7},{%8,%9},{%0,%1,%2,%3};"
        : "+f"(c[0]), "+f"(c[1]), "+f"(c[2]), "+f"(c[3])
        : "r"(a0), "r"(a1), "r"(a2), "r"(a3), "r"(b0), "r"(b1));
}

// truncation split: hi = top-16-bits bf16x2 (exact), lo = rn(residual) bf16x2
__device__ __forceinline__ void bsplit2(float f0, float f1, uint32_t& hi, uint32_t& lo){
    uint32_t u0 = __float_as_uint(f0), u1 = __float_as_uint(f1);
    asm("prmt.b32 %0, %1, %2, 0x7632;" : "=r"(hi) : "r"(u0), "r"(u1));
    float h0 = __uint_as_float(u0 & 0xffff0000u);
    float h1 = __uint_as_float(u1 & 0xffff0000u);
    float l0 = f0 - h0, l1 = f1 - h1;
    asm("cvt.rn.bf16x2.f32 %0, %1, %2;" : "=r"(lo) : "f"(l1), "f"(l0));
}

__global__ void __launch_bounds__(BLK, 3)
fused_kernel(const float* __restrict__ x,   const float* __restrict__ W1,
             const float* __restrict__ W2,  const float* __restrict__ Bb,
             const float* __restrict__ TW1, const float* __restrict__ TW,
             const float* __restrict__ TW2, const float* __restrict__ TB,
             const float* __restrict__ l,   float* __restrict__ out, int ntiles)
{
    extern __shared__ float sm[];
    uint32_t* smu = (uint32_t*)sm;
    const int tid  = threadIdx.x;
    const int wid  = tid >> 5;
    const int lane = tid & 31;

    auto stage = [&](long long tile){
        const float4* src = (const float4*)(x + tile * (SPT * D1v * T1v));
        #pragma unroll
        for (int it = 0; it < 10; it++) {
            int i = tid + it * BLK;          // 0..1599
            int s = i / 100;
            int o = i - s * 100;
            unsigned dst = (unsigned)__cvta_generic_to_shared(
                               sm + OXB + s * XSTR + o * 4);
            asm volatile("cp.async.cg.shared.global [%0], [%1], 16;"
                         :: "r"(dst), "l"(src + i));
        }
        asm volatile("cp.async.commit_group;");
    };

    const long long tile0 = blockIdx.x;
    if (tile0 < ntiles) stage(tile0);

    // ---- max_norm scales ----
    {
        const float* mp; int n;
        switch (wid) {
            case 0: mp = W1;  n = D2v*D1v; break;
            case 1: mp = TW1; n = D3v*D2v; break;
            case 2: mp = W2;  n = T1v*T2v; break;
            case 3: mp = TW;  n = T2v*T2v; break;
            default: mp = TW2; n = T2v;    break;
        }
        float s = 0.f;
        for (int i = lane; i < n; i += 32) { float v = mp[i]; s += v * v; }
        #pragma unroll
        for (int o = 16; o > 0; o >>= 1) s += __shfl_xor_sync(0xffffffffu, s, o);
        if (lane == 0) {
            float nn = sqrtf(s);
            sm[OSC + wid] = (nn > 10.f) ? (10.f / (1e-8f + nn)) : 1.f;
        }
    }
    __syncthreads();
    const float s1 = sm[OSC+0], s3 = sm[OSC+1], s2 = sm[OSC+2],
                s4 = sm[OSC+3], s5 = sm[OSC+4];

    // ---- build B frags in smem (prologue scratch) ----
    for (int i = tid; i < 15*NKT*32*2; i += BLK) {
        int rp = i & 1, li = (i >> 1) & 31;
        int ktc = (i >> 6) % NKT, nt = (i >> 6) / NKT;
        int g2 = li >> 2, tl2 = li & 3;
        int e  = nt*8 + g2;
        int k0 = ktc*16 + rp*8 + 2*tl2;
        float w0 = (k0   < D1v) ? W1[e*D1v + k0    ] * s1 : 0.f;
        float w1 = (k0+1 < D1v) ? W1[e*D1v + k0 + 1] * s1 : 0.f;
        uint32_t hi, lo; bsplit2(w0, w1, hi, lo);
        int word = ((nt*NKT + ktc)*32 + li)*2 + rp;
        smu[OW1F + word]        = hi;
        smu[OW1F + 2880 + word] = lo;
    }
    // zero A-frag padding (kt=2, rp=1 blocks: k 40..47), hi+lo, all strips
    for (int i = tid; i < 5*64; i += BLK) {
        int s = i >> 6, o = i & 63;
        int word = ((s*NKT + 2)*2 + 1)*ABLK + o;
        smu[OY1F + word]        = 0;
        smu[OY1F + 1980 + word] = 0;
    }
    for (int i = tid; i < 600; i += BLK) {
        int tt = i / 120, rem = i - tt*120;
        int p = rem >> 1, half = rem & 1;
        sm[OBIAS + (tt*60 + p)*2 + half] = Bb[(2*p + half)*T2v + tt];
    }
    for (int i = tid; i < 360; i += BLK) {
        int j = i / 120, rem = i - j*120;
        int p = rem >> 1, half = rem & 1;
        sm[OTW1 + (j*60 + p)*2 + half] = TW1[j*D2v + 2*p + half] * s3;
    }
    if (tid < 50)                     sm[OW2 + tid] = W2[tid] * s2;
    else if (tid >= 64 && tid < 89) {
        int i = tid - 64, r = i / 5, c2 = i - r*5;
        sm[OWM + i] = (r == c2) ? (1.f / T2v) : TW[i] * s4;
    }
    else if (tid >= 96  && tid < 101) sm[OW2B + (tid - 96)]  = TW2[tid - 96] * s5;
    else if (tid >= 104 && tid < 107) sm[OTB  + (tid - 104)] = TB[tid - 104];
    else if (tid == 112) {
        float lv = l[0];
        sm[OLAM] = fminf(fmaxf(lv, 0.f), 1.f);
    }
    __syncthreads();

    // ---- load this warp's B fragments into registers (3 nt x 3 kt, hi+lo) ----
    uint2 Bh[3][NKT], Blo[3][NKT];
    #pragma unroll
    for (int myn = 0; myn < 3; myn++)
        #pragma unroll
        for (int kt = 0; kt < NKT; kt++) {
            int nt = wid*3 + myn;
            int bbase = OW1F + ((nt*NKT + kt)*32 + lane)*2;
            Bh[myn][kt]  = *(const uint2*)(smu + bbase);
            Blo[myn][kt] = *(const uint2*)(smu + bbase + 2880);
        }
    __syncthreads();   // everyone has B; OW1F region now reusable as OPART

    // ---- GEMM1 / scatter constants: thread owns 4 d-rows of one sample ----
    const int samp = tid / 10;          // 0..15
    const int db   = tid - samp * 10;   // d-block 0..9 (rows db*4 .. db*4+3)
    // mma/epilogue constants
    const int g  = lane >> 2;
    const int tl = lane & 3;

    for (long long t = tile0; t < ntiles; t += gridDim.x) {
        asm volatile("cp.async.wait_group 0;" ::: "memory");
        __syncthreads();               // S1: x(t) visible; tail(t-1) done

        // ---- GEMM1: read x once, compute y[4][5] ----
        float xr[40];
        {
            const float4* xs = (const float4*)(sm + OXB) + samp*101 + db*10;
            #pragma unroll
            for (int j = 0; j < 10; j++) ((float4*)xr)[j] = xs[j];
        }
        float y[4][5];
        #pragma unroll
        for (int r = 0; r < 4; r++)
            #pragma unroll
            for (int tt = 0; tt < 5; tt++) y[r][tt] = 0.f;
        #pragma unroll
        for (int k = 0; k < 10; k++) {
            float wv[5];
            #pragma unroll
            for (int tt = 0; tt < 5; tt++) wv[tt] = sm[OW2 + k*5 + tt];
            #pragma unroll
            for (int r = 0; r < 4; r++) {
                float xv = xr[r*10 + k];
                #pragma unroll
                for (int tt = 0; tt < 5; tt++) y[r][tt] += xv * wv[tt];
            }
        }
        __syncthreads();               // S2: xbuf consumed; prior A-frag reads done

        if (t + gridDim.x < ntiles) stage(t + gridDim.x);   // overlap with mma

        // ---- scatter y to A-fragment layout ----
        #pragma unroll
        for (int tt = 0; tt < 5; tt++) {
            const int m     = samp*5 + tt;
            const int strip = m >> 4;
            const int r16   = m & 15;
            const int lbase = (r16 & 7)*8 + (r16 >> 3);
            #pragma unroll
            for (int p = 0; p < 2; p++) {
                const int p2   = db*2 + p;        // k-pair index, k = 2*p2
                const int kt   = p2 >> 3;
                const int rp   = (p2 >> 2) & 1;
                const int tsel = p2 & 3;
                const int word = ((strip*NKT + kt)*2 + rp)*ABLK + lbase + tsel*2;
                uint32_t hi, lo; bsplit2(y[2*p][tt], y[2*p+1][tt], hi, lo);
                smu[OY1F + word]        = hi;
                smu[OY1F + 1980 + word] = lo;
            }
        }
        __syncthreads();               // S3: A-frags ready

        // ---- mma: 3 nt (B in regs) x 5 strips, then per-strip epilogue ----
        float acc[5][3][4];
        #pragma unroll
        for (int s = 0; s < 5; s++)
            #pragma unroll
            for (int myn = 0; myn < 3; myn++) {
                acc[s][myn][0] = 0.f; acc[s][myn][1] = 0.f;
                acc[s][myn][2] = 0.f; acc[s][myn][3] = 0.f;
            }
        #pragma unroll
        for (int s = 0; s < 5; s++)
            #pragma unroll
            for (int kt = 0; kt < NKT; kt++) {
                const int abase = OY1F + ((s*NKT + kt)*2)*ABLK + lane*2;
                uint2 Ah01 = *(const uint2*)(smu + abase);
                uint2 Ah23 = *(const uint2*)(smu + abase + ABLK);
                uint2 Al01 = *(const uint2*)(smu + abase + 1980);
                uint2 Al23 = *(const uint2*)(smu + abase + 1980 + ABLK);
                #pragma unroll
                for (int myn = 0; myn < 3; myn++) {
                    mma16816(acc[s][myn], Ah01.x, Ah01.y, Ah23.x, Ah23.y,
                             Bh[myn][kt].x,  Bh[myn][kt].y);
                    mma16816(acc[s][myn], Ah01.x, Ah01.y, Ah23.x, Ah23.y,
                             Blo[myn][kt].x, Blo[myn][kt].y);
                    mma16816(acc[s][myn], Al01.x, Al01.y, Al23.x, Al23.y,
                             Bh[myn][kt].x,  Bh[myn][kt].y);
                }
            }

        // epilogue: bias+relu+partial X3 per strip; write part[row][j][wid]
        #pragma unroll
        for (int s = 0; s < 5; s++) {
            const int m0  = s*16 + g, m1 = m0 + 8;
            const int tt0 = m0 % 5, sl0 = m0 / 5;
            const int tt1 = m1 % 5, sl1 = m1 / 5;
            ull Xp[6] = {0,0,0,0,0,0};
            #pragma unroll
            for (int myn = 0; myn < 3; myn++) {
                const int pi = (wid*3 + myn)*4 + tl;
                float2 b0 = *(const float2*)(sm + OBIAS + (tt0*60 + pi)*2);
                float2 b1 = *(const float2*)(sm + OBIAS + (tt1*60 + pi)*2);
                float h00 = fmaxf(acc[s][myn][0] + b0.x, 0.f);
                float h01 = fmaxf(acc[s][myn][1] + b0.y, 0.f);
                float h10 = fmaxf(acc[s][myn][2] + b1.x, 0.f);
                float h11 = fmaxf(acc[s][myn][3] + b1.y, 0.f);
                ull hp0 = pk2(h00, h01), hp1 = pk2(h10, h11);
                #pragma unroll
                for (int j = 0; j < 3; j++) {
                    ull tw = *(const ull*)(sm + OTW1 + (j*60 + pi)*2);
                    Xp[j]   = ffma2(hp0, tw, Xp[j]);
                    Xp[3+j] = ffma2(hp1, tw, Xp[3+j]);
                }
            }
            #pragma unroll
            for (int j = 0; j < 3; j++) {
                float2 c0 = upk2(Xp[j]);
                float2 c1 = upk2(Xp[3+j]);
                float r0 = c0.x + c0.y;
                float r1 = c1.x + c1.y;
                r0 += __shfl_xor_sync(0xffffffffu, r0, 1);
                r0 += __shfl_xor_sync(0xffffffffu, r0, 2);
                r1 += __shfl_xor_sync(0xffffffffu, r1, 1);
                r1 += __shfl_xor_sync(0xffffffffu, r1, 2);
                if (tl == 0) {
                    sm[OPART + ((sl0*5 + tt0)*3 + j)*5 + wid] = r0;
                    sm[OPART + ((sl1*5 + tt1)*3 + j)*5 + wid] = r1;
                }
            }
        }
        __syncthreads();               // S4: partials ready

        // ---- per-sample tail (16 threads): sum 5 warp-partials + softmaxes ----
        if (tid < SPT) {
            float X[3][5];
            #pragma unroll
            for (int j = 0; j < 3; j++)
                #pragma unroll
                for (int tq = 0; tq < 5; tq++) {
                    const float* pp = sm + OPART + ((tid*5 + tq)*3 + j)*5;
                    X[j][tq] = pp[0] + pp[1] + pp[2] + pp[3] + pp[4];
                }

            const float lam = sm[OLAM];
            float o3[3];
            #pragma unroll
            for (int j = 0; j < 3; j++) {
                float P[5];
                #pragma unroll
                for (int tp = 0; tp < 5; tp++) {
                    float s = 0.f;
                    #pragma unroll
                    for (int tq = 0; tq < 5; tq++) s += X[j][tq] * sm[OWM + tq*5 + tp];
                    P[tp] = s;
                }
                float mx = P[0];
                #pragma unroll
                for (int tp = 1; tp < 5; tp++) mx = fmaxf(mx, P[tp]);
                float A[5]; float ssum = 0.f;
                #pragma unroll
                for (int tp = 0; tp < 5; tp++) { A[tp] = __expf(P[tp] - mx); ssum += A[tp]; }
                float inv = __fdividef(1.f, ssum);
                float acc2 = sm[OTB + j];
                #pragma unroll
                for (int tq = 0; tq < 5; tq++) {
                    float Xc = X[j][tq] * (lam + (1.f - lam) * A[tq] * inv);
                    acc2 += Xc * sm[OW2B + tq];
                }
                o3[j] = acc2;
            }
            float mx = fmaxf(o3[0], fmaxf(o3[1], o3[2]));
            float e0 = __expf(o3[0] - mx);
            float e1 = __expf(o3[1] - mx);
            float e2 = __expf(o3[2] - mx);
            float inv = __fdividef(1.f, e0 + e1 + e2);
            long long gs = t * SPT + tid;
            out[gs*3 + 0] = e0 * inv;
            out[gs*3 + 1] = e1 * inv;
            out[gs*3 + 2] = e2 * inv;
        }
        // next S1 orders tail(t) before part(t+1)/A-frag(t+1) writes
    }
}

// ------------------------------ launch --------------------------------------
extern "C" void kernel_launch(void* const* d_in, const int* in_sizes, int n_in,
                              void* d_out, int out_size)
{
    const float* x   = (const float*)d_in[0];
    const float* W1  = (const float*)d_in[1];
    const float* W2  = (const float*)d_in[2];
    const float* Bb  = (const float*)d_in[3];
    const float* TW1 = (const float*)d_in[4];
    const float* TW  = (const float*)d_in[5];
    const float* TW2 = (const float*)d_in[6];
    const float* TB  = (const float*)d_in[7];
    const float* l   = (const float*)d_in[8];

    const int nsamp  = in_sizes[0] / (D1v * T1v);   // 131072
    const int ntiles = nsamp / SPT;                 // 8192

    cudaFuncSetAttribute(fused_kernel, cudaFuncAttributeMaxDynamicSharedMemorySize,
                         SMW * 4);

    int grid = 456;                                 // 3 per SM on 152 SMs
    if (grid > ntiles) grid = ntiles;

    fused_kernel<<<grid, BLK, SMW * 4>>>(x, W1, W2, Bb, TW1, TW, TW2, TB, l,
                                         (float*)d_out, ntiles);
}

// round 9
// speedup vs baseline: 2.8646x; 1.0296x over previous
#include <cuda_runtime.h>
#include <math.h>
#include <stdint.h>

// ---------------------------------------------------------------------------
// m_btabl, R9: 32-sample tiles, 320 threads, 2 blocks/SM (20 warps/SM).
//  * warps 0-4 -> strips 0-4, warps 5-9 -> strips 5-9; each warp 3 n-tiles,
//    B fragments in registers (loaded once).
//  * per-strip mma with hoisted A frags and acc[3][4] only (reg cap ~96).
//  * read-once GEMM1 (thread owns 4 d-rows of one sample), stride-66 A layout.
//  * x staged via cp.async, overlapped under mma of previous tile.
// ---------------------------------------------------------------------------

#define D1v 40
#define T1v 10
#define D2v 120
#define T2v 5
#define D3v 3

#define BLK 320           // 10 warps
#define SPT 32            // samples per tile (160 rows, 10 m16-strips)
#define NKT 3             // 48/16 k-tiles
#define XSTR 404          // staged x row stride (floats)
#define ABLK 66           // A-frag block stride

// smem word offsets
#define OW1F  0                       // B frags hi 2880 / lo +2880 (PROLOGUE)
#define OPART 0                       // alias: partials [32][5][3][5] = 2400
#define OY1F  5760                    // A hi [10][3][2][66]=3960, lo +3960
#define OBIAS 13680                   // [tt5][pair60][2] = 600
#define OTW1  14280                   // [j3][pair60][2] = 360
#define OW2   14640                   // 50
#define OWM   14690                   // 25
#define OW2B  14715                   // 5
#define OTB   14720                   // 3
#define OLAM  14723                   // 1
#define OSC   14724                   // 6
#define OXB   14736                   // x buffer 32*404 = 12928 (16B aligned)
#define SMW   (OXB + SPT*XSTR)        // 27664 words = 110656 B

typedef unsigned long long ull;

__device__ __forceinline__ ull pk2(float lo, float hi){
    ull r; asm("mov.b64 %0, {%1,%2};" : "=l"(r) : "f"(lo), "f"(hi)); return r;
}
__device__ __forceinline__ float2 upk2(ull v){
    float2 r; asm("mov.b64 {%0,%1}, %2;" : "=f"(r.x), "=f"(r.y) : "l"(v)); return r;
}
__device__ __forceinline__ ull ffma2(ull a, ull b, ull c){
    ull d; asm("fma.rn.f32x2 %0, %1, %2, %3;" : "=l"(d) : "l"(a), "l"(b), "l"(c)); return d;
}

__device__ __forceinline__ void mma16816(float* c, uint32_t a0, uint32_t a1,
                                         uint32_t a2, uint32_t a3,
                                         uint32_t b0, uint32_t b1){
    asm("mma.sync.aligned.m16n8k16.row.col.f32.bf16.bf16.f32 "
        "{%0,%1,%2,%3},{%4,%5,%6,%7},{%8,%9},{%0,%1,%2,%3};"
        : "+f"(c[0]), "+f"(c[1]), "+f"(c[2]), "+f"(c[3])
        : "r"(a0), "r"(a1), "r"(a2), "r"(a3), "r"(b0), "r"(b1));
}

__device__ __forceinline__ void bsplit2(float f0, float f1, uint32_t& hi, uint32_t& lo){
    uint32_t u0 = __float_as_uint(f0), u1 = __float_as_uint(f1);
    asm("prmt.b32 %0, %1, %2, 0x7632;" : "=r"(hi) : "r"(u0), "r"(u1));
    float h0 = __uint_as_float(u0 & 0xffff0000u);
    float h1 = __uint_as_float(u1 & 0xffff0000u);
    float l0 = f0 - h0, l1 = f1 - h1;
    asm("cvt.rn.bf16x2.f32 %0, %1, %2;" : "=r"(lo) : "f"(l1), "f"(l0));
}

__global__ void __launch_bounds__(BLK, 2)
fused_kernel(const float* __restrict__ x,   const float* __restrict__ W1,
             const float* __restrict__ W2,  const float* __restrict__ Bb,
             const float* __restrict__ TW1, const float* __restrict__ TW,
             const float* __restrict__ TW2, const float* __restrict__ TB,
             const float* __restrict__ l,   float* __restrict__ out, int ntiles)
{
    extern __shared__ float sm[];
    uint32_t* smu = (uint32_t*)sm;
    const int tid  = threadIdx.x;
    const int wid  = tid >> 5;
    const int lane = tid & 31;

    auto stage = [&](long long tile){
        const float4* src = (const float4*)(x + tile * (SPT * D1v * T1v));
        #pragma unroll
        for (int it = 0; it < 10; it++) {
            int i = tid + it * BLK;          // 0..3199
            int s = i / 100;
            int o = i - s * 100;
            unsigned dst = (unsigned)__cvta_generic_to_shared(
                               sm + OXB + s * XSTR + o * 4);
            asm volatile("cp.async.cg.shared.global [%0], [%1], 16;"
                         :: "r"(dst), "l"(src + i));
        }
        asm volatile("cp.async.commit_group;");
    };

    const long long tile0 = blockIdx.x;
    if (tile0 < ntiles) stage(tile0);

    // ---- max_norm scales (warps 0..4 only) ----
    if (wid < 5) {
        const float* mp; int n;
        switch (wid) {
            case 0: mp = W1;  n = D2v*D1v; break;
            case 1: mp = TW1; n = D3v*D2v; break;
            case 2: mp = W2;  n = T1v*T2v; break;
            case 3: mp = TW;  n = T2v*T2v; break;
            default: mp = TW2; n = T2v;    break;
        }
        float s = 0.f;
        for (int i = lane; i < n; i += 32) { float v = mp[i]; s += v * v; }
        #pragma unroll
        for (int o = 16; o > 0; o >>= 1) s += __shfl_xor_sync(0xffffffffu, s, o);
        if (lane == 0) {
            float nn = sqrtf(s);
            sm[OSC + wid] = (nn > 10.f) ? (10.f / (1e-8f + nn)) : 1.f;
        }
    }
    __syncthreads();
    const float s1 = sm[OSC+0], s3 = sm[OSC+1], s2 = sm[OSC+2],
                s4 = sm[OSC+3], s5 = sm[OSC+4];

    // ---- build B frags in prologue scratch ----
    for (int i = tid; i < 15*NKT*32*2; i += BLK) {
        int rp = i & 1, li = (i >> 1) & 31;
        int ktc = (i >> 6) % NKT, nt = (i >> 6) / NKT;
        int g2 = li >> 2, tl2 = li & 3;
        int e  = nt*8 + g2;
        int k0 = ktc*16 + rp*8 + 2*tl2;
        float w0 = (k0   < D1v) ? W1[e*D1v + k0    ] * s1 : 0.f;
        float w1 = (k0+1 < D1v) ? W1[e*D1v + k0 + 1] * s1 : 0.f;
        uint32_t hi, lo; bsplit2(w0, w1, hi, lo);
        int word = ((nt*NKT + ktc)*32 + li)*2 + rp;
        smu[OW1F + word]        = hi;
        smu[OW1F + 2880 + word] = lo;
    }
    // zero A-frag padding (kt=2, rp=1), hi+lo, all 10 strips
    for (int i = tid; i < 10*64; i += BLK) {
        int s = i >> 6, o = i & 63;
        int word = ((s*NKT + 2)*2 + 1)*ABLK + o;
        smu[OY1F + word]        = 0;
        smu[OY1F + 3960 + word] = 0;
    }
    for (int i = tid; i < 600; i += BLK) {
        int tt = i / 120, rem = i - tt*120;
        int p = rem >> 1, half = rem & 1;
        sm[OBIAS + (tt*60 + p)*2 + half] = Bb[(2*p + half)*T2v + tt];
    }
    for (int i = tid; i < 360; i += BLK) {
        int j = i / 120, rem = i - j*120;
        int p = rem >> 1, half = rem & 1;
        sm[OTW1 + (j*60 + p)*2 + half] = TW1[j*D2v + 2*p + half] * s3;
    }
    if (tid < 50)                     sm[OW2 + tid] = W2[tid] * s2;
    else if (tid >= 64 && tid < 89) {
        int i = tid - 64, r = i / 5, c2 = i - r*5;
        sm[OWM + i] = (r == c2) ? (1.f / T2v) : TW[i] * s4;
    }
    else if (tid >= 96  && tid < 101) sm[OW2B + (tid - 96)]  = TW2[tid - 96] * s5;
    else if (tid >= 104 && tid < 107) sm[OTB  + (tid - 104)] = TB[tid - 104];
    else if (tid == 112) {
        float lv = l[0];
        sm[OLAM] = fminf(fmaxf(lv, 0.f), 1.f);
    }
    __syncthreads();

    // ---- this warp's B fragments (3 nt x 3 kt, hi+lo) in registers ----
    const int wg   = wid % 5;          // n-tile group
    const int half = wid / 5;          // strip half (0: strips 0-4, 1: 5-9)
    uint2 Bh[3][NKT], Blo[3][NKT];
    #pragma unroll
    for (int myn = 0; myn < 3; myn++)
        #pragma unroll
        for (int kt = 0; kt < NKT; kt++) {
            int nt = wg*3 + myn;
            int bbase = OW1F + ((nt*NKT + kt)*32 + lane)*2;
            Bh[myn][kt]  = *(const uint2*)(smu + bbase);
            Blo[myn][kt] = *(const uint2*)(smu + bbase + 2880);
        }
    __syncthreads();   // B consumed; OW1F reusable as OPART

    const int samp = tid / 10;          // 0..31
    const int db   = tid - samp * 10;   // d-block 0..9
    const int g  = lane >> 2;
    const int tl = lane & 3;

    for (long long t = tile0; t < ntiles; t += gridDim.x) {
        asm volatile("cp.async.wait_group 0;" ::: "memory");
        __syncthreads();               // S1: x(t) visible; tail(t-1) done

        // ---- GEMM1: read x once, compute y[4][5] ----
        float xr[40];
        {
            const float4* xs = (const float4*)(sm + OXB) + samp*101 + db*10;
            #pragma unroll
            for (int j = 0; j < 10; j++) ((float4*)xr)[j] = xs[j];
        }
        float y[4][5];
        #pragma unroll
        for (int r = 0; r < 4; r++)
            #pragma unroll
            for (int tt = 0; tt < 5; tt++) y[r][tt] = 0.f;
        #pragma unroll
        for (int k = 0; k < 10; k++) {
            float wv[5];
            #pragma unroll
            for (int tt = 0; tt < 5; tt++) wv[tt] = sm[OW2 + k*5 + tt];
            #pragma unroll
            for (int r = 0; r < 4; r++) {
                float xv = xr[r*10 + k];
                #pragma unroll
                for (int tt = 0; tt < 5; tt++) y[r][tt] += xv * wv[tt];
            }
        }
        __syncthreads();               // S2: xbuf consumed; prior A reads done

        if (t + gridDim.x < ntiles) stage(t + gridDim.x);   // overlap with mma

        // ---- scatter y to A-fragment layout ----
        #pragma unroll
        for (int tt = 0; tt < 5; tt++) {
            const int m     = samp*5 + tt;
            const int strip = m >> 4;
            const int r16   = m & 15;
            const int lbase = (r16 & 7)*8 + (r16 >> 3);
            #pragma unroll
            for (int p = 0; p < 2; p++) {
                const int p2   = db*2 + p;
                const int kt   = p2 >> 3;
                const int rp   = (p2 >> 2) & 1;
                const int tsel = p2 & 3;
                const int word = ((strip*NKT + kt)*2 + rp)*ABLK + lbase + tsel*2;
                uint32_t hi, lo; bsplit2(y[2*p][tt], y[2*p+1][tt], hi, lo);
                smu[OY1F + word]        = hi;
                smu[OY1F + 3960 + word] = lo;
            }
        }
        __syncthreads();               // S3: A-frags ready

        // ---- per-strip mma (A hoisted, acc[3][4]) + epilogue ----
        #pragma unroll
        for (int s = 0; s < 5; s++) {
            const int strip = half*5 + s;
            uint2 Ah01[NKT], Ah23[NKT], Al01[NKT], Al23[NKT];
            #pragma unroll
            for (int kt = 0; kt < NKT; kt++) {
                const int abase = OY1F + ((strip*NKT + kt)*2)*ABLK + lane*2;
                Ah01[kt] = *(const uint2*)(smu + abase);
                Ah23[kt] = *(const uint2*)(smu + abase + ABLK);
                Al01[kt] = *(const uint2*)(smu + abase + 3960);
                Al23[kt] = *(const uint2*)(smu + abase + 3960 + ABLK);
            }
            float acc[3][4];
            #pragma unroll
            for (int myn = 0; myn < 3; myn++) {
                acc[myn][0] = 0.f; acc[myn][1] = 0.f;
                acc[myn][2] = 0.f; acc[myn][3] = 0.f;
            }
            #pragma unroll
            for (int kt = 0; kt < NKT; kt++)
                #pragma unroll
                for (int myn = 0; myn < 3; myn++) {
                    mma16816(acc[myn], Ah01[kt].x, Ah01[kt].y, Ah23[kt].x, Ah23[kt].y,
                             Bh[myn][kt].x,  Bh[myn][kt].y);
                    mma16816(acc[myn], Ah01[kt].x, Ah01[kt].y, Ah23[kt].x, Ah23[kt].y,
                             Blo[myn][kt].x, Blo[myn][kt].y);
                    mma16816(acc[myn], Al01[kt].x, Al01[kt].y, Al23[kt].x, Al23[kt].y,
                             Bh[myn][kt].x,  Bh[myn][kt].y);
                }

            const int m0  = strip*16 + g, m1 = m0 + 8;
            const int tt0 = m0 % 5, sl0 = m0 / 5;
            const int tt1 = m1 % 5, sl1 = m1 / 5;
            ull Xp[6] = {0,0,0,0,0,0};
            #pragma unroll
            for (int myn = 0; myn < 3; myn++) {
                const int pi = (wg*3 + myn)*4 + tl;
                float2 b0 = *(const float2*)(sm + OBIAS + (tt0*60 + pi)*2);
                float2 b1 = *(const float2*)(sm + OBIAS + (tt1*60 + pi)*2);
                float h00 = fmaxf(acc[myn][0] + b0.x, 0.f);
                float h01 = fmaxf(acc[myn][1] + b0.y, 0.f);
                float h10 = fmaxf(acc[myn][2] + b1.x, 0.f);
                float h11 = fmaxf(acc[myn][3] + b1.y, 0.f);
                ull hp0 = pk2(h00, h01), hp1 = pk2(h10, h11);
                #pragma unroll
                for (int j = 0; j < 3; j++) {
                    ull tw = *(const ull*)(sm + OTW1 + (j*60 + pi)*2);
                    Xp[j]   = ffma2(hp0, tw, Xp[j]);
                    Xp[3+j] = ffma2(hp1, tw, Xp[3+j]);
                }
            }
            #pragma unroll
            for (int j = 0; j < 3; j++) {
                float2 c0 = upk2(Xp[j]);
                float2 c1 = upk2(Xp[3+j]);
                float r0 = c0.x + c0.y;
                float r1 = c1.x + c1.y;
                r0 += __shfl_xor_sync(0xffffffffu, r0, 1);
                r0 += __shfl_xor_sync(0xffffffffu, r0, 2);
                r1 += __shfl_xor_sync(0xffffffffu, r1, 1);
                r1 += __shfl_xor_sync(0xffffffffu, r1, 2);
                if (tl == 0) {
                    sm[OPART + ((sl0*5 + tt0)*3 + j)*5 + wg] = r0;
                    sm[OPART + ((sl1*5 + tt1)*3 + j)*5 + wg] = r1;
                }
            }
        }
        __syncthreads();               // S4: partials ready

        // ---- per-sample tail (32 threads) ----
        if (tid < SPT) {
            float X[3][5];
            #pragma unroll
            for (int j = 0; j < 3; j++)
                #pragma unroll
                for (int tq = 0; tq < 5; tq++) {
                    const float* pp = sm + OPART + ((tid*5 + tq)*3 + j)*5;
                    X[j][tq] = pp[0] + pp[1] + pp[2] + pp[3] + pp[4];
                }

            const float lam = sm[OLAM];
            float o3[3];
            #pragma unroll
            for (int j = 0; j < 3; j++) {
                float P[5];
                #pragma unroll
                for (int tp = 0; tp < 5; tp++) {
                    float s = 0.f;
                    #pragma unroll
                    for (int tq = 0; tq < 5; tq++) s += X[j][tq] * sm[OWM + tq*5 + tp];
                    P[tp] = s;
                }
                float mx = P[0];
                #pragma unroll
                for (int tp = 1; tp < 5; tp++) mx = fmaxf(mx, P[tp]);
                float A[5]; float ssum = 0.f;
                #pragma unroll
                for (int tp = 0; tp < 5; tp++) { A[tp] = __expf(P[tp] - mx); ssum += A[tp]; }
                float inv = __fdividef(1.f, ssum);
                float acc2 = sm[OTB + j];
                #pragma unroll
                for (int tq = 0; tq < 5; tq++) {
                    float Xc = X[j][tq] * (lam + (1.f - lam) * A[tq] * inv);
                    acc2 += Xc * sm[OW2B + tq];
                }
                o3[j] = acc2;
            }
            float mx = fmaxf(o3[0], fmaxf(o3[1], o3[2]));
            float e0 = __expf(o3[0] - mx);
            float e1 = __expf(o3[1] - mx);
            float e2 = __expf(o3[2] - mx);
            float inv = __fdividef(1.f, e0 + e1 + e2);
            long long gs = t * SPT + tid;
            out[gs*3 + 0] = e0 * inv;
            out[gs*3 + 1] = e1 * inv;
            out[gs*3 + 2] = e2 * inv;
        }
        // next S1 orders tail(t) before writes of tile t+1
    }
}

// ------------------------------ launch --------------------------------------
extern "C" void kernel_launch(void* const* d_in, const int* in_sizes, int n_in,
                              void* d_out, int out_size)
{
    const float* x   = (const float*)d_in[0];
    const float* W1  = (const float*)d_in[1];
    const float* W2  = (const float*)d_in[2];
    const float* Bb  = (const float*)d_in[3];
    const float* TW1 = (const float*)d_in[4];
    const float* TW  = (const float*)d_in[5];
    const float* TW2 = (const float*)d_in[6];
    const float* TB  = (const float*)d_in[7];
    const float* l   = (const float*)d_in[8];

    const int nsamp  = in_sizes[0] / (D1v * T1v);   // 131072
    const int ntiles = nsamp / SPT;                 // 4096

    cudaFuncSetAttribute(fused_kernel, cudaFuncAttributeMaxDynamicSharedMemorySize,
                         SMW * 4);

    int grid = 304;                                 // 2 per SM on 152 SMs
    if (grid > ntiles) grid = ntiles;

    fused_kernel<<<grid, BLK, SMW * 4>>>(x, W1, W2, Bb, TW1, TW, TW2, TB, l,
                                         (float*)d_out, ntiles);
}

// round 10
// speedup vs baseline: 3.1850x; 1.1118x over previous
#include <cuda_runtime.h>
#include <math.h>
#include <stdint.h>

// ---------------------------------------------------------------------------
// m_btabl, R10: bias folded into MMA (one-hot K-augmentation), vectorized W2T,
// uint4 A-fragment layout.
//  * A[m][40+tt(m)] = 1 (bf16, prologue-constant); B[40+tt'][e] = BL_B[e][tt']
//    -> bias comes out of the tensor core; epilogue is relu(acc) only.
//  * GEMM1: read-once x, W2T[5][12] vectorized broadcasts, scatter per tt.
//  * A frags [strip10][kt3][lane32][4 words], hi/lo: 1 LDS.128 per (s,kt) each.
//  * 320 thr, 2 blocks/SM, warps = (nt-group wg 0..4) x (strip-half 0..1),
//    B frags in registers.
// ---------------------------------------------------------------------------

#define D1v 40
#define T1v 10
#define D2v 120
#define T2v 5
#define D3v 3

#define BLK 320
#define SPT 32            // samples per tile (160 rows, 10 strips)
#define NKT 3
#define XSTR 404

// smem word offsets
#define OW1F  0                       // B frags hi 2880 / lo +2880 (PROLOGUE)
#define OPART 0                       // alias after prologue: [32][5][3][5]=2400
#define OY1F  5760                    // A hi [10][3][32][4]=3840, lo +3840
#define OTW1  13440                   // [j3][pair60][2] = 360
#define OW2T  13800                   // [tt5][12] = 60
#define OWM   13860                   // 25
#define OW2B  13885                   // 5
#define OTB   13890                   // 3
#define OLAM  13893                   // 1
#define OSC   13894                   // 6
#define OXB   13904                   // x buffer 32*404 = 12928 (16B aligned)
#define SMW   (OXB + SPT*XSTR)        // 26832 words = 107328 B

typedef unsigned long long ull;

__device__ __forceinline__ ull pk2(float lo, float hi){
    ull r; asm("mov.b64 %0, {%1,%2};" : "=l"(r) : "f"(lo), "f"(hi)); return r;
}
__device__ __forceinline__ float2 upk2(ull v){
    float2 r; asm("mov.b64 {%0,%1}, %2;" : "=f"(r.x), "=f"(r.y) : "l"(v)); return r;
}
__device__ __forceinline__ ull ffma2(ull a, ull b, ull c){
    ull d; asm("fma.rn.f32x2 %0, %1, %2, %3;" : "=l"(d) : "l"(a), "l"(b), "l"(c)); return d;
}

__device__ __forceinline__ void mma16816(float* c, uint32_t a0, uint32_t a1,
                                         uint32_t a2, uint32_t a3,
                                         uint32_t b0, uint32_t b1){
    asm("mma.sync.aligned.m16n8k16.row.col.f32.bf16.bf16.f32 "
        "{%0,%1,%2,%3},{%4,%5,%6,%7},{%8,%9},{%0,%1,%2,%3};"
        : "+f"(c[0]), "+f"(c[1]), "+f"(c[2]), "+f"(c[3])
        : "r"(a0), "r"(a1), "r"(a2), "r"(a3), "r"(b0), "r"(b1));
}

__device__ __forceinline__ void bsplit2(float f0, float f1, uint32_t& hi, uint32_t& lo){
    uint32_t u0 = __float_as_uint(f0), u1 = __float_as_uint(f1);
    asm("prmt.b32 %0, %1, %2, 0x7632;" : "=r"(hi) : "r"(u0), "r"(u1));
    float h0 = __uint_as_float(u0 & 0xffff0000u);
    float h1 = __uint_as_float(u1 & 0xffff0000u);
    float l0 = f0 - h0, l1 = f1 - h1;
    asm("cvt.rn.bf16x2.f32 %0, %1, %2;" : "=r"(lo) : "f"(l1), "f"(l0));
}

__global__ void __launch_bounds__(BLK, 2)
fused_kernel(const float* __restrict__ x,   const float* __restrict__ W1,
             const float* __restrict__ W2,  const float* __restrict__ Bb,
             const float* __restrict__ TW1, const float* __restrict__ TW,
             const float* __restrict__ TW2, const float* __restrict__ TB,
             const float* __restrict__ l,   float* __restrict__ out, int ntiles)
{
    extern __shared__ float sm[];
    uint32_t* smu = (uint32_t*)sm;
    const int tid  = threadIdx.x;
    const int wid  = tid >> 5;
    const int lane = tid & 31;

    auto stage = [&](long long tile){
        const float4* src = (const float4*)(x + tile * (SPT * D1v * T1v));
        #pragma unroll
        for (int it = 0; it < 10; it++) {
            int i = tid + it * BLK;
            int s = i / 100;
            int o = i - s * 100;
            unsigned dst = (unsigned)__cvta_generic_to_shared(
                               sm + OXB + s * XSTR + o * 4);
            asm volatile("cp.async.cg.shared.global [%0], [%1], 16;"
                         :: "r"(dst), "l"(src + i));
        }
        asm volatile("cp.async.commit_group;");
    };

    const long long tile0 = blockIdx.x;
    if (tile0 < ntiles) stage(tile0);

    // ---- max_norm scales ----
    if (wid < 5) {
        const float* mp; int n;
        switch (wid) {
            case 0: mp = W1;  n = D2v*D1v; break;
            case 1: mp = TW1; n = D3v*D2v; break;
            case 2: mp = W2;  n = T1v*T2v; break;
            case 3: mp = TW;  n = T2v*T2v; break;
            default: mp = TW2; n = T2v;    break;
        }
        float s = 0.f;
        for (int i = lane; i < n; i += 32) { float v = mp[i]; s += v * v; }
        #pragma unroll
        for (int o = 16; o > 0; o >>= 1) s += __shfl_xor_sync(0xffffffffu, s, o);
        if (lane == 0) {
            float nn = sqrtf(s);
            sm[OSC + wid] = (nn > 10.f) ? (10.f / (1e-8f + nn)) : 1.f;
        }
    }
    __syncthreads();
    const float s1 = sm[OSC+0], s3 = sm[OSC+1], s2 = sm[OSC+2],
                s4 = sm[OSC+3], s5 = sm[OSC+4];

    // ---- build B frags: W1 (scaled) for k<40, BL_B bias rows for k=40..44 ----
    for (int i = tid; i < 15*NKT*32*2; i += BLK) {
        int rp = i & 1, li = (i >> 1) & 31;
        int ktc = (i >> 6) % NKT, nt = (i >> 6) / NKT;
        int g2 = li >> 2, tl2 = li & 3;
        int e  = nt*8 + g2;
        int k0 = ktc*16 + rp*8 + 2*tl2;
        float w0, w1;
        if (k0 < D1v) {
            w0 = W1[e*D1v + k0] * s1;
            w1 = (k0+1 < D1v) ? W1[e*D1v + k0 + 1] * s1 : 0.f;
        } else {                           // bias rows: k = 40 + tt'
            int tt0 = k0 - D1v, tt1 = tt0 + 1;
            w0 = (tt0 < T2v) ? Bb[e*T2v + tt0] : 0.f;
            w1 = (tt1 < T2v) ? Bb[e*T2v + tt1] : 0.f;
        }
        uint32_t hi, lo; bsplit2(w0, w1, hi, lo);
        int word = ((nt*NKT + ktc)*32 + li)*2 + rp;
        smu[OW1F + word]        = hi;
        smu[OW1F + 2880 + word] = lo;
    }
    // zero A-frag kt=2, khalf=1 (idx 2,3) region, hi+lo (one-hot set below)
    for (int i = tid; i < 10*32*2; i += BLK) {
        int s = i / 64, rem = i - s*64;
        int li = rem >> 1, idx = 2 + (rem & 1);
        int word = ((s*NKT + 2)*32 + li)*4 + idx;
        smu[OY1F + word]        = 0;
        smu[OY1F + 3840 + word] = 0;
    }
    for (int i = tid; i < 360; i += BLK) {
        int j = i / 120, rem = i - j*120;
        int p = rem >> 1, half = rem & 1;
        sm[OTW1 + (j*60 + p)*2 + half] = TW1[j*D2v + 2*p + half] * s3;
    }
    for (int i = tid; i < 60; i += BLK) {
        int tt = i / 12, k = i - tt*12;
        sm[OW2T + i] = (k < T1v) ? W2[k*T2v + tt] * s2 : 0.f;
    }
    if (tid >= 64 && tid < 89) {
        int i = tid - 64, r = i / 5, c2 = i - r*5;
        sm[OWM + i] = (r == c2) ? (1.f / T2v) : TW[i] * s4;
    }
    else if (tid >= 96  && tid < 101) sm[OW2B + (tid - 96)]  = TW2[tid - 96] * s5;
    else if (tid >= 104 && tid < 107) sm[OTB  + (tid - 104)] = TB[tid - 104];
    else if (tid == 112) {
        float lv = l[0];
        sm[OLAM] = fminf(fmaxf(lv, 0.f), 1.f);
    }
    __syncthreads();

    // ---- one-hot bias selectors in A (constant across tiles) ----
    if (tid < 160) {
        int m = tid, tt = m % 5;
        int strip = m >> 4, r16 = m & 15;
        int g2 = r16 & 7, rowhalf = r16 >> 3, tl2 = tt >> 1;
        int word = ((strip*NKT + 2)*32 + g2*4 + tl2)*4 + rowhalf + 2;
        smu[OY1F + word] = (tt & 1) ? 0x3F800000u : 0x00003F80u;  // bf16 1.0
    }
    // this warp's B fragments (3 nt x 3 kt, hi+lo)
    const int wg   = wid % 5;
    const int half = wid / 5;
    uint2 Bh[3][NKT], Blo[3][NKT];
    #pragma unroll
    for (int myn = 0; myn < 3; myn++)
        #pragma unroll
        for (int kt = 0; kt < NKT; kt++) {
            int nt = wg*3 + myn;
            int bbase = OW1F + ((nt*NKT + kt)*32 + lane)*2;
            Bh[myn][kt]  = *(const uint2*)(smu + bbase);
            Blo[myn][kt] = *(const uint2*)(smu + bbase + 2880);
        }
    __syncthreads();   // B consumed; OW1F reusable as OPART; one-hots visible

    const int samp = tid / 10;
    const int db   = tid - samp * 10;
    const int g  = lane >> 2;
    const int tl = lane & 3;

    for (long long t = tile0; t < ntiles; t += gridDim.x) {
        asm volatile("cp.async.wait_group 0;" ::: "memory");
        __syncthreads();               // S1: x(t) visible; tail(t-1) done

        // ---- GEMM1: read x once; per tt compute + scatter immediately ----
        float xr[40];
        {
            const float4* xs = (const float4*)(sm + OXB) + samp*101 + db*10;
            #pragma unroll
            for (int j = 0; j < 10; j++) ((float4*)xr)[j] = xs[j];
        }
        #pragma unroll
        for (int tt = 0; tt < 5; tt++) {
            float w[12];
            #pragma unroll
            for (int j = 0; j < 3; j++)
                ((float4*)w)[j] = *(const float4*)(sm + OW2T + tt*12 + j*4);
            float y4[4];
            #pragma unroll
            for (int r = 0; r < 4; r++) {
                float a = xr[r*10 + 0] * w[0];
                #pragma unroll
                for (int k = 1; k < 10; k++) a += xr[r*10 + k] * w[k];
                y4[r] = a;
            }
            const int m     = samp*5 + tt;
            const int strip = m >> 4;
            const int r16   = m & 15;
            const int g2    = r16 & 7, rowhalf = r16 >> 3;
            #pragma unroll
            for (int p = 0; p < 2; p++) {
                const int p2    = db*2 + p;
                const int kt    = p2 >> 3;
                const int q8    = p2 & 7;
                const int khalf = q8 >> 2, tl2 = q8 & 3;
                const int word  = ((strip*NKT + kt)*32 + g2*4 + tl2)*4
                                  + rowhalf + khalf*2;
                uint32_t hi, lo; bsplit2(y4[2*p], y4[2*p+1], hi, lo);
                smu[OY1F + word]        = hi;
                smu[OY1F + 3840 + word] = lo;
            }
        }
        __syncthreads();               // S2: xbuf consumed + A-frags ready

        if (t + gridDim.x < ntiles) stage(t + gridDim.x);   // overlap with mma

        // ---- per-strip mma + epilogue ----
        #pragma unroll
        for (int s = 0; s < 5; s++) {
            const int strip = half*5 + s;
            float acc[3][4];
            #pragma unroll
            for (int myn = 0; myn < 3; myn++) {
                acc[myn][0] = 0.f; acc[myn][1] = 0.f;
                acc[myn][2] = 0.f; acc[myn][3] = 0.f;
            }
            #pragma unroll
            for (int kt = 0; kt < NKT; kt++) {
                const int abase = ((strip*NKT + kt)*32 + lane)*4;
                uint4 Ah = *(const uint4*)(smu + OY1F + abase);
                uint4 Al = *(const uint4*)(smu + OY1F + 3840 + abase);
                #pragma unroll
                for (int myn = 0; myn < 3; myn++) {
                    mma16816(acc[myn], Ah.x, Ah.y, Ah.z, Ah.w,
                             Bh[myn][kt].x,  Bh[myn][kt].y);
                    mma16816(acc[myn], Ah.x, Ah.y, Ah.z, Ah.w,
                             Blo[myn][kt].x, Blo[myn][kt].y);
                    mma16816(acc[myn], Al.x, Al.y, Al.z, Al.w,
                             Bh[myn][kt].x,  Bh[myn][kt].y);
                }
            }
            const int m0  = strip*16 + g, m1 = m0 + 8;
            const int tt0 = m0 % 5, sl0 = m0 / 5;
            const int tt1 = m1 % 5, sl1 = m1 / 5;
            ull Xp[6] = {0,0,0,0,0,0};
            #pragma unroll
            for (int myn = 0; myn < 3; myn++) {
                const int pi = (wg*3 + myn)*4 + tl;
                float h00 = fmaxf(acc[myn][0], 0.f);   // bias already in acc
                float h01 = fmaxf(acc[myn][1], 0.f);
                float h10 = fmaxf(acc[myn][2], 0.f);
                float h11 = fmaxf(acc[myn][3], 0.f);
                ull hp0 = pk2(h00, h01), hp1 = pk2(h10, h11);
                #pragma unroll
                for (int j = 0; j < 3; j++) {
                    ull tw = *(const ull*)(sm + OTW1 + (j*60 + pi)*2);
                    Xp[j]   = ffma2(hp0, tw, Xp[j]);
                    Xp[3+j] = ffma2(hp1, tw, Xp[3+j]);
                }
            }
            #pragma unroll
            for (int j = 0; j < 3; j++) {
                float2 c0 = upk2(Xp[j]);
                float2 c1 = upk2(Xp[3+j]);
                float r0 = c0.x + c0.y;
                float r1 = c1.x + c1.y;
                r0 += __shfl_xor_sync(0xffffffffu, r0, 1);
                r0 += __shfl_xor_sync(0xffffffffu, r0, 2);
                r1 += __shfl_xor_sync(0xffffffffu, r1, 1);
                r1 += __shfl_xor_sync(0xffffffffu, r1, 2);
                if (tl == 0) {
                    sm[OPART + ((sl0*5 + tt0)*3 + j)*5 + wg] = r0;
                    sm[OPART + ((sl1*5 + tt1)*3 + j)*5 + wg] = r1;
                }
            }
        }
        __syncthreads();               // S3: partials ready

        // ---- per-sample tail (32 threads) ----
        if (tid < SPT) {
            float X[3][5];
            #pragma unroll
            for (int j = 0; j < 3; j++)
                #pragma unroll
                for (int tq = 0; tq < 5; tq++) {
                    const float* pp = sm + OPART + ((tid*5 + tq)*3 + j)*5;
                    X[j][tq] = pp[0] + pp[1] + pp[2] + pp[3] + pp[4];
                }

            const float lam = sm[OLAM];
            float o3[3];
            #pragma unroll
            for (int j = 0; j < 3; j++) {
                float P[5];
                #pragma unroll
                for (int tp = 0; tp < 5; tp++) {
                    float s = 0.f;
                    #pragma unroll
                    for (int tq = 0; tq < 5; tq++) s += X[j][tq] * sm[OWM + tq*5 + tp];
                    P[tp] = s;
                }
                float mx = P[0];
                #pragma unroll
                for (int tp = 1; tp < 5; tp++) mx = fmaxf(mx, P[tp]);
                float A[5]; float ssum = 0.f;
                #pragma unroll
                for (int tp = 0; tp < 5; tp++) { A[tp] = __expf(P[tp] - mx); ssum += A[tp]; }
                float inv = __fdividef(1.f, ssum);
                float acc2 = sm[OTB + j];
                #pragma unroll
                for (int tq = 0; tq < 5; tq++) {
                    float Xc = X[j][tq] * (lam + (1.f - lam) * A[tq] * inv);
                    acc2 += Xc * sm[OW2B + tq];
                }
                o3[j] = acc2;
            }
            float mx = fmaxf(o3[0], fmaxf(o3[1], o3[2]));
            float e0 = __expf(o3[0] - mx);
            float e1 = __expf(o3[1] - mx);
            float e2 = __expf(o3[2] - mx);
            float inv = __fdividef(1.f, e0 + e1 + e2);
            long long gs = t * SPT + tid;
            out[gs*3 + 0] = e0 * inv;
            out[gs*3 + 1] = e1 * inv;
            out[gs*3 + 2] = e2 * inv;
        }
        // next S1 orders tail(t) before tile t+1 writes
    }
}

// ------------------------------ launch --------------------------------------
extern "C" void kernel_launch(void* const* d_in, const int* in_sizes, int n_in,
                              void* d_out, int out_size)
{
    const float* x   = (const float*)d_in[0];
    const float* W1  = (const float*)d_in[1];
    const float* W2  = (const float*)d_in[2];
    const float* Bb  = (const float*)d_in[3];
    const float* TW1 = (const float*)d_in[4];
    const float* TW  = (const float*)d_in[5];
    const float* TW2 = (const float*)d_in[6];
    const float* TB  = (const float*)d_in[7];
    const float* l   = (const float*)d_in[8];

    const int nsamp  = in_sizes[0] / (D1v * T1v);   // 131072
    const int ntiles = nsamp / SPT;                 // 4096

    cudaFuncSetAttribute(fused_kernel, cudaFuncAttributeMaxDynamicSharedMemorySize,
                         SMW * 4);

    int grid = 304;
    if (grid > ntiles) grid = ntiles;

    fused_kernel<<<grid, BLK, SMW * 4>>>(x, W1, W2, Bb, TW1, TW, TW2, TB, l,
                                         (float*)d_out, ntiles);
}

// round 11
// speedup vs baseline: 3.2275x; 1.0133x over previous
#include <cuda_runtime.h>
#include <math.h>
#include <stdint.h>

// ---------------------------------------------------------------------------
// m_btabl, R11: software-pipelined tiles (double-buffered A-fragments).
//  Body(t): [wait; S1] GEMM1(t+1)->scatter A[buf^1]  +  mma(A[buf])->partials(t)
//           [S2] stage x(t+2); tail(t).
//  2 barriers/tile; LSU and tensor phases share each barrier interval.
//  16-sample tiles, 160 threads, 3 blocks/SM (15 warps), bias folded in MMA,
//  B frags + epilogue tw in registers, B-scratch aliased into x buffer.
// ---------------------------------------------------------------------------

#define D1v 40
#define T1v 10
#define D2v 120
#define T2v 5
#define D3v 3

#define BLK 160
#define SPT 16            // samples per tile (80 rows, 5 strips)
#define NKT 3
#define XSTR 404

// smem word offsets
#define OA    0                       // A frags: buf{0,1} x (hi 1920 | lo 1920) = 7680
#define OXB   7680                    // x buffer 16*404 = 6464 ; aliases B-scratch (5760)
#define OPART 14144                   // [16][5][3][5] = 1200
#define OTW1  15344                   // [j3][pair60][2] = 360
#define OW2T  15704                   // [tt5][12] = 60
#define OWM   15764                   // 25
#define OW2B  15789                   // 5
#define OTB   15794                   // 3
#define OLAM  15797                   // 1
#define OSC   15798                   // 6
#define SMW   15808                   // 63232 B

typedef unsigned long long ull;

__device__ __forceinline__ ull pk2(float lo, float hi){
    ull r; asm("mov.b64 %0, {%1,%2};" : "=l"(r) : "f"(lo), "f"(hi)); return r;
}
__device__ __forceinline__ float2 upk2(ull v){
    float2 r; asm("mov.b64 {%0,%1}, %2;" : "=f"(r.x), "=f"(r.y) : "l"(v)); return r;
}
__device__ __forceinline__ ull ffma2(ull a, ull b, ull c){
    ull d; asm("fma.rn.f32x2 %0, %1, %2, %3;" : "=l"(d) : "l"(a), "l"(b), "l"(c)); return d;
}

__device__ __forceinline__ void mma16816(float* c, uint32_t a0, uint32_t a1,
                                         uint32_t a2, uint32_t a3,
                                         uint32_t b0, uint32_t b1){
    asm("mma.sync.aligned.m16n8k16.row.col.f32.bf16.bf16.f32 "
        "{%0,%1,%2,%3},{%4,%5,%6,%7},{%8,%9},{%0,%1,%2,%3};"
        : "+f"(c[0]), "+f"(c[1]), "+f"(c[2]), "+f"(c[3])
        : "r"(a0), "r"(a1), "r"(a2), "r"(a3), "r"(b0), "r"(b1));
}

__device__ __forceinline__ void bsplit2(float f0, float f1, uint32_t& hi, uint32_t& lo){
    uint32_t u0 = __float_as_uint(f0), u1 = __float_as_uint(f1);
    asm("prmt.b32 %0, %1, %2, 0x7632;" : "=r"(hi) : "r"(u0), "r"(u1));
    float h0 = __uint_as_float(u0 & 0xffff0000u);
    float h1 = __uint_as_float(u1 & 0xffff0000u);
    float l0 = f0 - h0, l1 = f1 - h1;
    asm("cvt.rn.bf16x2.f32 %0, %1, %2;" : "=r"(lo) : "f"(l1), "f"(l0));
}

__global__ void __launch_bounds__(BLK, 3)
fused_kernel(const float* __restrict__ x,   const float* __restrict__ W1,
             const float* __restrict__ W2,  const float* __restrict__ Bb,
             const float* __restrict__ TW1, const float* __restrict__ TW,
             const float* __restrict__ TW2, const float* __restrict__ TB,
             const float* __restrict__ l,   float* __restrict__ out, int ntiles)
{
    extern __shared__ float sm[];
    uint32_t* smu = (uint32_t*)sm;
    const int tid  = threadIdx.x;
    const int wid  = tid >> 5;
    const int lane = tid & 31;

    auto stage = [&](long long tile){
        const float4* src = (const float4*)(x + tile * (SPT * D1v * T1v));
        #pragma unroll
        for (int it = 0; it < 10; it++) {
            int i = tid + it * BLK;          // 0..1599
            int s = i / 100;
            int o = i - s * 100;
            unsigned dst = (unsigned)__cvta_generic_to_shared(
                               sm + OXB + s * XSTR + o * 4);
            asm volatile("cp.async.cg.shared.global [%0], [%1], 16;"
                         :: "r"(dst), "l"(src + i));
        }
        asm volatile("cp.async.commit_group;");
    };

    // ---- max_norm scales (5 warps = 5 matrices) ----
    {
        const float* mp; int n;
        switch (wid) {
            case 0: mp = W1;  n = D2v*D1v; break;
            case 1: mp = TW1; n = D3v*D2v; break;
            case 2: mp = W2;  n = T1v*T2v; break;
            case 3: mp = TW;  n = T2v*T2v; break;
            default: mp = TW2; n = T2v;    break;
        }
        float s = 0.f;
        for (int i = lane; i < n; i += 32) { float v = mp[i]; s += v * v; }
        #pragma unroll
        for (int o = 16; o > 0; o >>= 1) s += __shfl_xor_sync(0xffffffffu, s, o);
        if (lane == 0) {
            float nn = sqrtf(s);
            sm[OSC + wid] = (nn > 10.f) ? (10.f / (1e-8f + nn)) : 1.f;
        }
    }
    __syncthreads();
    const float s1 = sm[OSC+0], s3 = sm[OSC+1], s2 = sm[OSC+2],
                s4 = sm[OSC+3], s5 = sm[OSC+4];

    // ---- build B frags (W1 rows + bias rows) in x-buffer scratch ----
    for (int i = tid; i < 15*NKT*32*2; i += BLK) {
        int rp = i & 1, li = (i >> 1) & 31;
        int ktc = (i >> 6) % NKT, nt = (i >> 6) / NKT;
        int g2 = li >> 2, tl2 = li & 3;
        int e  = nt*8 + g2;
        int k0 = ktc*16 + rp*8 + 2*tl2;
        float w0, w1;
        if (k0 < D1v) {
            w0 = W1[e*D1v + k0] * s1;
            w1 = (k0+1 < D1v) ? W1[e*D1v + k0 + 1] * s1 : 0.f;
        } else {
            int tt0 = k0 - D1v, tt1 = tt0 + 1;
            w0 = (tt0 < T2v) ? Bb[e*T2v + tt0] : 0.f;
            w1 = (tt1 < T2v) ? Bb[e*T2v + tt1] : 0.f;
        }
        uint32_t hi, lo; bsplit2(w0, w1, hi, lo);
        int word = ((nt*NKT + ktc)*32 + li)*2 + rp;
        smu[OXB + word]        = hi;
        smu[OXB + 2880 + word] = lo;
    }
    for (int i = tid; i < 360; i += BLK) {
        int j = i / 120, rem = i - j*120;
        int p = rem >> 1, half2 = rem & 1;
        sm[OTW1 + (j*60 + p)*2 + half2] = TW1[j*D2v + 2*p + half2] * s3;
    }
    for (int i = tid; i < 60; i += BLK) {
        int tt = i / 12, k = i - tt*12;
        sm[OW2T + i] = (k < T1v) ? W2[k*T2v + tt] * s2 : 0.f;
    }
    if (tid >= 64 && tid < 89) {
        int i = tid - 64, r = i / 5, c2 = i - r*5;
        sm[OWM + i] = (r == c2) ? (1.f / T2v) : TW[i] * s4;
    }
    else if (tid >= 96  && tid < 101) sm[OW2B + (tid - 96)]  = TW2[tid - 96] * s5;
    else if (tid >= 104 && tid < 107) sm[OTB  + (tid - 104)] = TB[tid - 104];
    else if (tid == 112) {
        float lv = l[0];
        sm[OLAM] = fminf(fmaxf(lv, 0.f), 1.f);
    }
    __syncthreads();

    // ---- hoist B frags (3 nt x 3 kt, hi+lo) and epilogue tw into registers ----
    const int g  = lane >> 2;
    const int tl = lane & 3;
    uint2 Bh[3][NKT], Blo[3][NKT];
    ull   twr[3][3];                   // [myn][j]
    #pragma unroll
    for (int myn = 0; myn < 3; myn++) {
        #pragma unroll
        for (int kt = 0; kt < NKT; kt++) {
            int nt = wid*3 + myn;
            int bbase = OXB + ((nt*NKT + kt)*32 + lane)*2;
            Bh[myn][kt]  = *(const uint2*)(smu + bbase);
            Blo[myn][kt] = *(const uint2*)(smu + bbase + 2880);
        }
        const int pi = (wid*3 + myn)*4 + tl;
        #pragma unroll
        for (int j = 0; j < 3; j++)
            twr[myn][j] = *(const ull*)(sm + OTW1 + (j*60 + pi)*2);
    }
    __syncthreads();                   // B-scratch (x region) free

    // ---- A-frag constants: zero k=45..47 pads + one-hot bias selectors ----
    for (int i = tid; i < 1280; i += BLK) {      // 5 strips x 32 x {2,3} x hi/lo x buf
        int buf = i & 1;
        int hl  = (i >> 1) & 1;
        int idx = 2 + ((i >> 2) & 1);
        int li  = (i >> 3) & 31;
        int s   = i >> 8;
        smu[OA + buf*3840 + hl*1920 + ((s*NKT + 2)*32 + li)*4 + idx] = 0;
    }
    if (tid < 160) {                              // one-hot: 80 rows x 2 bufs
        int buf = (tid >= 80) ? 1 : 0;
        int m   = tid - buf*80;
        int tt  = m % 5;
        int strip = m >> 4, r16 = m & 15;
        int g2 = r16 & 7, rowhalf = r16 >> 3, tl2 = tt >> 1;
        int word = OA + buf*3840 + ((strip*NKT + 2)*32 + g2*4 + tl2)*4 + rowhalf + 2;
        smu[word] = (tt & 1) ? 0x3F800000u : 0x00003F80u;   // bf16 1.0
    }

    const long long step = gridDim.x;
    const long long t0   = blockIdx.x;
    const int samp = tid / 10;
    const int db   = tid - samp * 10;

    // GEMM1 + scatter into A[buf] for tile `tile`
    auto gemm1_scatter = [&](int buf){
        float xr[40];
        const float4* xs = (const float4*)(sm + OXB) + samp*101 + db*10;
        #pragma unroll
        for (int j = 0; j < 10; j++) ((float4*)xr)[j] = xs[j];
        #pragma unroll
        for (int tt = 0; tt < 5; tt++) {
            float w[12];
            #pragma unroll
            for (int j = 0; j < 3; j++)
                ((float4*)w)[j] = *(const float4*)(sm + OW2T + tt*12 + j*4);
            float y4[4];
            #pragma unroll
            for (int r = 0; r < 4; r++) {
                float a = xr[r*10 + 0] * w[0];
                #pragma unroll
                for (int k = 1; k < 10; k++) a += xr[r*10 + k] * w[k];
                y4[r] = a;
            }
            const int m     = samp*5 + tt;
            const int strip = m >> 4;
            const int r16   = m & 15;
            const int g2    = r16 & 7, rowhalf = r16 >> 3;
            #pragma unroll
            for (int p = 0; p < 2; p++) {
                const int p2    = db*2 + p;
                const int kt    = p2 >> 3;
                const int q8    = p2 & 7;
                const int khalf = q8 >> 2, tl2 = q8 & 3;
                const int word  = OA + buf*3840
                                  + ((strip*NKT + kt)*32 + g2*4 + tl2)*4
                                  + rowhalf + khalf*2;
                uint32_t hi, lo; bsplit2(y4[2*p], y4[2*p+1], hi, lo);
                smu[word]        = hi;
                smu[word + 1920] = lo;
            }
        }
    };

    // ---- pipeline prologue: tile t0 -> A[0]; stage t0+step ----
    if (t0 < ntiles) stage(t0);
    asm volatile("cp.async.wait_group 0;" ::: "memory");
    __syncthreads();                   // x(t0) + A one-hots visible
    if (t0 < ntiles) gemm1_scatter(0);
    __syncthreads();                   // A[0] ready; x consumed
    if (t0 + step < ntiles) stage(t0 + step);

    int buf = 0;
    for (long long t = t0; t < ntiles; t += step) {
        const long long tn = t + step;
        asm volatile("cp.async.wait_group 0;" ::: "memory");
        __syncthreads();               // S1: x(tn) visible; tail(t-1) done; A[buf^1] free

        if (tn < ntiles) gemm1_scatter(buf ^ 1);   // LSU work

        // ---- mma(A[buf]) over 5 strips + epilogue (tensor work) ----
        #pragma unroll
        for (int s = 0; s < 5; s++) {
            float acc[3][4];
            #pragma unroll
            for (int myn = 0; myn < 3; myn++) {
                acc[myn][0] = 0.f; acc[myn][1] = 0.f;
                acc[myn][2] = 0.f; acc[myn][3] = 0.f;
            }
            #pragma unroll
            for (int kt = 0; kt < NKT; kt++) {
                const int abase = OA + buf*3840 + ((s*NKT + kt)*32 + lane)*4;
                uint4 Ah = *(const uint4*)(smu + abase);
                uint4 Al = *(const uint4*)(smu + abase + 1920);
                #pragma unroll
                for (int myn = 0; myn < 3; myn++) {
                    mma16816(acc[myn], Ah.x, Ah.y, Ah.z, Ah.w,
                             Bh[myn][kt].x,  Bh[myn][kt].y);
                    mma16816(acc[myn], Ah.x, Ah.y, Ah.z, Ah.w,
                             Blo[myn][kt].x, Blo[myn][kt].y);
                    mma16816(acc[myn], Al.x, Al.y, Al.z, Al.w,
                             Bh[myn][kt].x,  Bh[myn][kt].y);
                }
            }
            const int m0  = s*16 + g, m1 = m0 + 8;
            const int tt0 = m0 % 5, sl0 = m0 / 5;
            const int tt1 = m1 % 5, sl1 = m1 / 5;
            ull Xp[6] = {0,0,0,0,0,0};
            #pragma unroll
            for (int myn = 0; myn < 3; myn++) {
                float h00 = fmaxf(acc[myn][0], 0.f);
                float h01 = fmaxf(acc[myn][1], 0.f);
                float h10 = fmaxf(acc[myn][2], 0.f);
                float h11 = fmaxf(acc[myn][3], 0.f);
                ull hp0 = pk2(h00, h01), hp1 = pk2(h10, h11);
                #pragma unroll
                for (int j = 0; j < 3; j++) {
                    Xp[j]   = ffma2(hp0, twr[myn][j], Xp[j]);
                    Xp[3+j] = ffma2(hp1, twr[myn][j], Xp[3+j]);
                }
            }
            #pragma unroll
            for (int j = 0; j < 3; j++) {
                float2 c0 = upk2(Xp[j]);
                float2 c1 = upk2(Xp[3+j]);
                float r0 = c0.x + c0.y;
                float r1 = c1.x + c1.y;
                r0 += __shfl_xor_sync(0xffffffffu, r0, 1);
                r0 += __shfl_xor_sync(0xffffffffu, r0, 2);
                r1 += __shfl_xor_sync(0xffffffffu, r1, 1);
                r1 += __shfl_xor_sync(0xffffffffu, r1, 2);
                if (tl == 0) {
                    sm[OPART + ((sl0*5 + tt0)*3 + j)*5 + wid] = r0;
                    sm[OPART + ((sl1*5 + tt1)*3 + j)*5 + wid] = r1;
                }
            }
        }
        __syncthreads();               // S2: partials ready; GEMM1 x-reads done

        if (tn + step < ntiles) stage(tn + step);   // overlap with tail + next GEMM1

        if (tid < SPT) {
            float X[3][5];
            #pragma unroll
            for (int j = 0; j < 3; j++)
                #pragma unroll
                for (int tq = 0; tq < 5; tq++) {
                    const float* pp = sm + OPART + ((tid*5 + tq)*3 + j)*5;
                    X[j][tq] = pp[0] + pp[1] + pp[2] + pp[3] + pp[4];
                }
            const float lam = sm[OLAM];
            float o3[3];
            #pragma unroll
            for (int j = 0; j < 3; j++) {
                float P[5];
                #pragma unroll
                for (int tp = 0; tp < 5; tp++) {
                    float s = 0.f;
                    #pragma unroll
                    for (int tq = 0; tq < 5; tq++) s += X[j][tq] * sm[OWM + tq*5 + tp];
                    P[tp] = s;
                }
                float mx = P[0];
                #pragma unroll
                for (int tp = 1; tp < 5; tp++) mx = fmaxf(mx, P[tp]);
                float A[5]; float ssum = 0.f;
                #pragma unroll
                for (int tp = 0; tp < 5; tp++) { A[tp] = __expf(P[tp] - mx); ssum += A[tp]; }
                float inv = __fdividef(1.f, ssum);
                float acc2 = sm[OTB + j];
                #pragma unroll
                for (int tq = 0; tq < 5; tq++) {
                    float Xc = X[j][tq] * (lam + (1.f - lam) * A[tq] * inv);
                    acc2 += Xc * sm[OW2B + tq];
                }
                o3[j] = acc2;
            }
            float mx = fmaxf(o3[0], fmaxf(o3[1], o3[2]));
            float e0 = __expf(o3[0] - mx);
            float e1 = __expf(o3[1] - mx);
            float e2 = __expf(o3[2] - mx);
            float inv = __fdividef(1.f, e0 + e1 + e2);
            long long gs = t * SPT + tid;
            out[gs*3 + 0] = e0 * inv;
            out[gs*3 + 1] = e1 * inv;
            out[gs*3 + 2] = e2 * inv;
        }
        buf ^= 1;
        // next S1 orders tail(t) before partials(t+step)/A writes
    }
}

// ------------------------------ launch --------------------------------------
extern "C" void kernel_launch(void* const* d_in, const int* in_sizes, int n_in,
                              void* d_out, int out_size)
{
    const float* x   = (const float*)d_in[0];
    const float* W1  = (const float*)d_in[1];
    const float* W2  = (const float*)d_in[2];
    const float* Bb  = (const float*)d_in[3];
    const float* TW1 = (const float*)d_in[4];
    const float* TW  = (const float*)d_in[5];
    const float* TW2 = (const float*)d_in[6];
    const float* TB  = (const float*)d_in[7];
    const float* l   = (const float*)d_in[8];

    const int nsamp  = in_sizes[0] / (D1v * T1v);   // 131072
    const int ntiles = nsamp / SPT;                 // 8192

    cudaFuncSetAttribute(fused_kernel, cudaFuncAttributeMaxDynamicSharedMemorySize,
                         SMW * 4);

    int grid = 456;                                 // 3 per SM on 152 SMs
    if (grid > ntiles) grid = ntiles;

    fused_kernel<<<grid, BLK, SMW * 4>>>(x, W1, W2, Bb, TW1, TW, TW2, TB, l,
                                         (float*)d_out, ntiles);
}

// round 12
// speedup vs baseline: 3.2284x; 1.0003x over previous
#include <cuda_runtime.h>
#include <math.h>
#include <stdint.h>

// ---------------------------------------------------------------------------
// m_btabl, R11: software-pipelined tiles (double-buffered A-fragments).
//  Body(t): [wait; S1] GEMM1(t+1)->scatter A[buf^1]  +  mma(A[buf])->partials(t)
//           [S2] stage x(t+2); tail(t).
//  2 barriers/tile; LSU and tensor phases share each barrier interval.
//  16-sample tiles, 160 threads, 3 blocks/SM (15 warps), bias folded in MMA,
//  B frags + epilogue tw in registers, B-scratch aliased into x buffer.
// ---------------------------------------------------------------------------

#define D1v 40
#define T1v 10
#define D2v 120
#define T2v 5
#define D3v 3

#define BLK 160
#define SPT 16            // samples per tile (80 rows, 5 strips)
#define NKT 3
#define XSTR 404

// smem word offsets
#define OA    0                       // A frags: buf{0,1} x (hi 1920 | lo 1920) = 7680
#define OXB   7680                    // x buffer 16*404 = 6464 ; aliases B-scratch (5760)
#define OPART 14144                   // [16][5][3][5] = 1200
#define OTW1  15344                   // [j3][pair60][2] = 360
#define OW2T  15704                   // [tt5][12] = 60
#define OWM   15764                   // 25
#define OW2B  15789                   // 5
#define OTB   15794                   // 3
#define OLAM  15797                   // 1
#define OSC   15798                   // 6
#define SMW   15808                   // 63232 B

typedef unsigned long long ull;

__device__ __forceinline__ ull pk2(float lo, float hi){
    ull r; asm("mov.b64 %0, {%1,%2};" : "=l"(r) : "f"(lo), "f"(hi)); return r;
}
__device__ __forceinline__ float2 upk2(ull v){
    float2 r; asm("mov.b64 {%0,%1}, %2;" : "=f"(r.x), "=f"(r.y) : "l"(v)); return r;
}
__device__ __forceinline__ ull ffma2(ull a, ull b, ull c){
    ull d; asm("fma.rn.f32x2 %0, %1, %2, %3;" : "=l"(d) : "l"(a), "l"(b), "l"(c)); return d;
}

__device__ __forceinline__ void mma16816(float* c, uint32_t a0, uint32_t a1,
                                         uint32_t a2, uint32_t a3,
                                         uint32_t b0, uint32_t b1){
    asm("mma.sync.aligned.m16n8k16.row.col.f32.bf16.bf16.f32 "
        "{%0,%1,%2,%3},{%4,%5,%6,%7},{%8,%9},{%0,%1,%2,%3};"
        : "+f"(c[0]), "+f"(c[1]), "+f"(c[2]), "+f"(c[3])
        : "r"(a0), "r"(a1), "r"(a2), "r"(a3), "r"(b0), "r"(b1));
}

__device__ __forceinline__ void bsplit2(float f0, float f1, uint32_t& hi, uint32_t& lo){
    uint32_t u0 = __float_as_uint(f0), u1 = __float_as_uint(f1);
    asm("prmt.b32 %0, %1, %2, 0x7632;" : "=r"(hi) : "r"(u0), "r"(u1));
    float h0 = __uint_as_float(u0 & 0xffff0000u);
    float h1 = __uint_as_float(u1 & 0xffff0000u);
    float l0 = f0 - h0, l1 = f1 - h1;
    asm("cvt.rn.bf16x2.f32 %0, %1, %2;" : "=r"(lo) : "f"(l1), "f"(l0));
}

__global__ void __launch_bounds__(BLK, 3)
fused_kernel(const float* __restrict__ x,   const float* __restrict__ W1,
             const float* __restrict__ W2,  const float* __restrict__ Bb,
             const float* __restrict__ TW1, const float* __restrict__ TW,
             const float* __restrict__ TW2, const float* __restrict__ TB,
             const float* __restrict__ l,   float* __restrict__ out, int ntiles)
{
    extern __shared__ float sm[];
    uint32_t* smu = (uint32_t*)sm;
    const int tid  = threadIdx.x;
    const int wid  = tid >> 5;
    const int lane = tid & 31;

    auto stage = [&](long long tile){
        const float4* src = (const float4*)(x + tile * (SPT * D1v * T1v));
        #pragma unroll
        for (int it = 0; it < 10; it++) {
            int i = tid + it * BLK;          // 0..1599
            int s = i / 100;
            int o = i - s * 100;
            unsigned dst = (unsigned)__cvta_generic_to_shared(
                               sm + OXB + s * XSTR + o * 4);
            asm volatile("cp.async.cg.shared.global [%0], [%1], 16;"
                         :: "r"(dst), "l"(src + i));
        }
        asm volatile("cp.async.commit_group;");
    };

    // ---- max_norm scales (5 warps = 5 matrices) ----
    {
        const float* mp; int n;
        switch (wid) {
            case 0: mp = W1;  n = D2v*D1v; break;
            case 1: mp = TW1; n = D3v*D2v; break;
            case 2: mp = W2;  n = T1v*T2v; break;
            case 3: mp = TW;  n = T2v*T2v; break;
            default: mp = TW2; n = T2v;    break;
        }
        float s = 0.f;
        for (int i = lane; i < n; i += 32) { float v = mp[i]; s += v * v; }
        #pragma unroll
        for (int o = 16; o > 0; o >>= 1) s += __shfl_xor_sync(0xffffffffu, s, o);
        if (lane == 0) {
            float nn = sqrtf(s);
            sm[OSC + wid] = (nn > 10.f) ? (10.f / (1e-8f + nn)) : 1.f;
        }
    }
    __syncthreads();
    const float s1 = sm[OSC+0], s3 = sm[OSC+1], s2 = sm[OSC+2],
                s4 = sm[OSC+3], s5 = sm[OSC+4];

    // ---- build B frags (W1 rows + bias rows) in x-buffer scratch ----
    for (int i = tid; i < 15*NKT*32*2; i += BLK) {
        int rp = i & 1, li = (i >> 1) & 31;
        int ktc = (i >> 6) % NKT, nt = (i >> 6) / NKT;
        int g2 = li >> 2, tl2 = li & 3;
        int e  = nt*8 + g2;
        int k0 = ktc*16 + rp*8 + 2*tl2;
        float w0, w1;
        if (k0 < D1v) {
            w0 = W1[e*D1v + k0] * s1;
            w1 = (k0+1 < D1v) ? W1[e*D1v + k0 + 1] * s1 : 0.f;
        } else {
            int tt0 = k0 - D1v, tt1 = tt0 + 1;
            w0 = (tt0 < T2v) ? Bb[e*T2v + tt0] : 0.f;
            w1 = (tt1 < T2v) ? Bb[e*T2v + tt1] : 0.f;
        }
        uint32_t hi, lo; bsplit2(w0, w1, hi, lo);
        int word = ((nt*NKT + ktc)*32 + li)*2 + rp;
        smu[OXB + word]        = hi;
        smu[OXB + 2880 + word] = lo;
    }
    for (int i = tid; i < 360; i += BLK) {
        int j = i / 120, rem = i - j*120;
        int p = rem >> 1, half2 = rem & 1;
        sm[OTW1 + (j*60 + p)*2 + half2] = TW1[j*D2v + 2*p + half2] * s3;
    }
    for (int i = tid; i < 60; i += BLK) {
        int tt = i / 12, k = i - tt*12;
        sm[OW2T + i] = (k < T1v) ? W2[k*T2v + tt] * s2 : 0.f;
    }
    if (tid >= 64 && tid < 89) {
        int i = tid - 64, r = i / 5, c2 = i - r*5;
        sm[OWM + i] = (r == c2) ? (1.f / T2v) : TW[i] * s4;
    }
    else if (tid >= 96  && tid < 101) sm[OW2B + (tid - 96)]  = TW2[tid - 96] * s5;
    else if (tid >= 104 && tid < 107) sm[OTB  + (tid - 104)] = TB[tid - 104];
    else if (tid == 112) {
        float lv = l[0];
        sm[OLAM] = fminf(fmaxf(lv, 0.f), 1.f);
    }
    __syncthreads();

    // ---- hoist B frags (3 nt x 3 kt, hi+lo) and epilogue tw into registers ----
    const int g  = lane >> 2;
    const int tl = lane & 3;
    uint2 Bh[3][NKT], Blo[3][NKT];
    ull   twr[3][3];                   // [myn][j]
    #pragma unroll
    for (int myn = 0; myn < 3; myn++) {
        #pragma unroll
        for (int kt = 0; kt < NKT; kt++) {
            int nt = wid*3 + myn;
            int bbase = OXB + ((nt*NKT + kt)*32 + lane)*2;
            Bh[myn][kt]  = *(const uint2*)(smu + bbase);
            Blo[myn][kt] = *(const uint2*)(smu + bbase + 2880);
        }
        const int pi = (wid*3 + myn)*4 + tl;
        #pragma unroll
        for (int j = 0; j < 3; j++)
            twr[myn][j] = *(const ull*)(sm + OTW1 + (j*60 + pi)*2);
    }
    __syncthreads();                   // B-scratch (x region) free

    // ---- A-frag constants: zero k=45..47 pads + one-hot bias selectors ----
    for (int i = tid; i < 1280; i += BLK) {      // 5 strips x 32 x {2,3} x hi/lo x buf
        int buf = i & 1;
        int hl  = (i >> 1) & 1;
        int idx = 2 + ((i >> 2) & 1);
        int li  = (i >> 3) & 31;
        int s   = i >> 8;
        smu[OA + buf*3840 + hl*1920 + ((s*NKT + 2)*32 + li)*4 + idx] = 0;
    }
    if (tid < 160) {                              // one-hot: 80 rows x 2 bufs
        int buf = (tid >= 80) ? 1 : 0;
        int m   = tid - buf*80;
        int tt  = m % 5;
        int strip = m >> 4, r16 = m & 15;
        int g2 = r16 & 7, rowhalf = r16 >> 3, tl2 = tt >> 1;
        int word = OA + buf*3840 + ((strip*NKT + 2)*32 + g2*4 + tl2)*4 + rowhalf + 2;
        smu[word] = (tt & 1) ? 0x3F800000u : 0x00003F80u;   // bf16 1.0
    }

    const long long step = gridDim.x;
    const long long t0   = blockIdx.x;
    const int samp = tid / 10;
    const int db   = tid - samp * 10;

    // GEMM1 + scatter into A[buf] for tile `tile`
    auto gemm1_scatter = [&](int buf){
        float xr[40];
        const float4* xs = (const float4*)(sm + OXB) + samp*101 + db*10;
        #pragma unroll
        for (int j = 0; j < 10; j++) ((float4*)xr)[j] = xs[j];
        #pragma unroll
        for (int tt = 0; tt < 5; tt++) {
            float w[12];
            #pragma unroll
            for (int j = 0; j < 3; j++)
                ((float4*)w)[j] = *(const float4*)(sm + OW2T + tt*12 + j*4);
            float y4[4];
            #pragma unroll
            for (int r = 0; r < 4; r++) {
                float a = xr[r*10 + 0] * w[0];
                #pragma unroll
                for (int k = 1; k < 10; k++) a += xr[r*10 + k] * w[k];
                y4[r] = a;
            }
            const int m     = samp*5 + tt;
            const int strip = m >> 4;
            const int r16   = m & 15;
            const int g2    = r16 & 7, rowhalf = r16 >> 3;
            #pragma unroll
            for (int p = 0; p < 2; p++) {
                const int p2    = db*2 + p;
                const int kt    = p2 >> 3;
                const int q8    = p2 & 7;
                const int khalf = q8 >> 2, tl2 = q8 & 3;
                const int word  = OA + buf*3840
                                  + ((strip*NKT + kt)*32 + g2*4 + tl2)*4
                                  + rowhalf + khalf*2;
                uint32_t hi, lo; bsplit2(y4[2*p], y4[2*p+1], hi, lo);
                smu[word]        = hi;
                smu[word + 1920] = lo;
            }
        }
    };

    // ---- pipeline prologue: tile t0 -> A[0]; stage t0+step ----
    if (t0 < ntiles) stage(t0);
    asm volatile("cp.async.wait_group 0;" ::: "memory");
    __syncthreads();                   // x(t0) + A one-hots visible
    if (t0 < ntiles) gemm1_scatter(0);
    __syncthreads();                   // A[0] ready; x consumed
    if (t0 + step < ntiles) stage(t0 + step);

    int buf = 0;
    for (long long t = t0; t < ntiles; t += step) {
        const long long tn = t + step;
        asm volatile("cp.async.wait_group 0;" ::: "memory");
        __syncthreads();               // S1: x(tn) visible; tail(t-1) done; A[buf^1] free

        if (tn < ntiles) gemm1_scatter(buf ^ 1);   // LSU work

        // ---- mma(A[buf]) over 5 strips + epilogue (tensor work) ----
        #pragma unroll
        for (int s = 0; s < 5; s++) {
            float acc[3][4];
            #pragma unroll
            for (int myn = 0; myn < 3; myn++) {
                acc[myn][0] = 0.f; acc[myn][1] = 0.f;
                acc[myn][2] = 0.f; acc[myn][3] = 0.f;
            }
            #pragma unroll
            for (int kt = 0; kt < NKT; kt++) {
                const int abase = OA + buf*3840 + ((s*NKT + kt)*32 + lane)*4;
                uint4 Ah = *(const uint4*)(smu + abase);
                uint4 Al = *(const uint4*)(smu + abase + 1920);
                #pragma unroll
                for (int myn = 0; myn < 3; myn++) {
                    mma16816(acc[myn], Ah.x, Ah.y, Ah.z, Ah.w,
                             Bh[myn][kt].x,  Bh[myn][kt].y);
                    mma16816(acc[myn], Ah.x, Ah.y, Ah.z, Ah.w,
                             Blo[myn][kt].x, Blo[myn][kt].y);
                    mma16816(acc[myn], Al.x, Al.y, Al.z, Al.w,
                             Bh[myn][kt].x,  Bh[myn][kt].y);
                }
            }
            const int m0  = s*16 + g, m1 = m0 + 8;
            const int tt0 = m0 % 5, sl0 = m0 / 5;
            const int tt1 = m1 % 5, sl1 = m1 / 5;
            ull Xp[6] = {0,0,0,0,0,0};
            #pragma unroll
            for (int myn = 0; myn < 3; myn++) {
                float h00 = fmaxf(acc[myn][0], 0.f);
                float h01 = fmaxf(acc[myn][1], 0.f);
                float h10 = fmaxf(acc[myn][2], 0.f);
                float h11 = fmaxf(acc[myn][3], 0.f);
                ull hp0 = pk2(h00, h01), hp1 = pk2(h10, h11);
                #pragma unroll
                for (int j = 0; j < 3; j++) {
                    Xp[j]   = ffma2(hp0, twr[myn][j], Xp[j]);
                    Xp[3+j] = ffma2(hp1, twr[myn][j], Xp[3+j]);
                }
            }
            #pragma unroll
            for (int j = 0; j < 3; j++) {
                float2 c0 = upk2(Xp[j]);
                float2 c1 = upk2(Xp[3+j]);
                float r0 = c0.x + c0.y;
                float r1 = c1.x + c1.y;
                r0 += __shfl_xor_sync(0xffffffffu, r0, 1);
                r0 += __shfl_xor_sync(0xffffffffu, r0, 2);
                r1 += __shfl_xor_sync(0xffffffffu, r1, 1);
                r1 += __shfl_xor_sync(0xffffffffu, r1, 2);
                if (tl == 0) {
                    sm[OPART + ((sl0*5 + tt0)*3 + j)*5 + wid] = r0;
                    sm[OPART + ((sl1*5 + tt1)*3 + j)*5 + wid] = r1;
                }
            }
        }
        __syncthreads();               // S2: partials ready; GEMM1 x-reads done

        if (tn + step < ntiles) stage(tn + step);   // overlap with tail + next GEMM1

        if (tid < SPT) {
            float X[3][5];
            #pragma unroll
            for (int j = 0; j < 3; j++)
                #pragma unroll
                for (int tq = 0; tq < 5; tq++) {
                    const float* pp = sm + OPART + ((tid*5 + tq)*3 + j)*5;
                    X[j][tq] = pp[0] + pp[1] + pp[2] + pp[3] + pp[4];
                }
            const float lam = sm[OLAM];
            float o3[3];
            #pragma unroll
            for (int j = 0; j < 3; j++) {
                float P[5];
                #pragma unroll
                for (int tp = 0; tp < 5; tp++) {
                    float s = 0.f;
                    #pragma unroll
                    for (int tq = 0; tq < 5; tq++) s += X[j][tq] * sm[OWM + tq*5 + tp];
                    P[tp] = s;
                }
                float mx = P[0];
                #pragma unroll
                for (int tp = 1; tp < 5; tp++) mx = fmaxf(mx, P[tp]);
                float A[5]; float ssum = 0.f;
                #pragma unroll
                for (int tp = 0; tp < 5; tp++) { A[tp] = __expf(P[tp] - mx); ssum += A[tp]; }
                float inv = __fdividef(1.f, ssum);
                float acc2 = sm[OTB + j];
                #pragma unroll
                for (int tq = 0; tq < 5; tq++) {
                    float Xc = X[j][tq] * (lam + (1.f - lam) * A[tq] * inv);
                    acc2 += Xc * sm[OW2B + tq];
                }
                o3[j] = acc2;
            }
            float mx = fmaxf(o3[0], fmaxf(o3[1], o3[2]));
            float e0 = __expf(o3[0] - mx);
            float e1 = __expf(o3[1] - mx);
            float e2 = __expf(o3[2] - mx);
            float inv = __fdividef(1.f, e0 + e1 + e2);
            long long gs = t * SPT + tid;
            out[gs*3 + 0] = e0 * inv;
            out[gs*3 + 1] = e1 * inv;
            out[gs*3 + 2] = e2 * inv;
        }
        buf ^= 1;
        // next S1 orders tail(t) before partials(t+step)/A writes
    }
}

// ------------------------------ launch --------------------------------------
extern "C" void kernel_launch(void* const* d_in, const int* in_sizes, int n_in,
                              void* d_out, int out_size)
{
    const float* x   = (const float*)d_in[0];
    const float* W1  = (const float*)d_in[1];
    const float* W2  = (const float*)d_in[2];
    const float* Bb  = (const float*)d_in[3];
    const float* TW1 = (const float*)d_in[4];
    const float* TW  = (const float*)d_in[5];
    const float* TW2 = (const float*)d_in[6];
    const float* TB  = (const float*)d_in[7];
    const float* l   = (const float*)d_in[8];

    const int nsamp  = in_sizes[0] / (D1v * T1v);   // 131072
    const int ntiles = nsamp / SPT;                 // 8192

    cudaFuncSetAttribute(fused_kernel, cudaFuncAttributeMaxDynamicSharedMemorySize,
                         SMW * 4);

    int grid = 456;                                 // 3 per SM on 152 SMs
    if (grid > ntiles) grid = ntiles;

    fused_kernel<<<grid, BLK, SMW * 4>>>(x, W1, W2, Bb, TW1, TW, TW2, TB, l,
                                         (float*)d_out, ntiles);
}